// round 1
// baseline (speedup 1.0000x reference)
#include <cuda_runtime.h>
#include <math.h>

#define BATCH 32
#define SEQ   2048
#define DQ    1024
#define DV    1024
#define UN    1024
#define ROWS  (BATCH * SEQ)

// Scratch (device globals — no allocation allowed)
__device__ float g_projq[BATCH * UN];
__device__ float g_score[BATCH * SEQ];

// Accurate-enough fast tanh: 2 MUFU (ex2 + rcp) + a few FMA, ~1e-6 rel err.
__device__ __forceinline__ float fast_tanh(float x) {
    float ax = fabsf(x);
    float e  = __expf(2.0f * ax);         // inf for huge ax -> t = 1 exactly
    float t  = 1.0f - 2.0f / (e + 1.0f);
    return copysignf(t, x);
}

// ---------------------------------------------------------------------------
// K1: proj_q[b,u] = query[b,:] . W2[:,u] + b2[u]        grid(4, 32) x 256
// ---------------------------------------------------------------------------
__global__ void projq_kernel(const float* __restrict__ q,
                             const float* __restrict__ W2,
                             const float* __restrict__ b2) {
    const int u = blockIdx.x * 256 + threadIdx.x;
    const int b = blockIdx.y;
    const float* qb = q + b * DQ;
    float acc = b2[u];
#pragma unroll 8
    for (int d = 0; d < DQ; ++d)
        acc = fmaf(qb[d], W2[d * UN + u], acc);
    g_projq[b * UN + u] = acc;
}

// ---------------------------------------------------------------------------
// K2: fused score kernel.
// score[row] = sum_u V[u] * tanh( values[row,:] . W1[:,u] + b1[u] + projq[b,u] )
// 128x128x8 tiled SGEMM core, 8 u-tiles looped per block, epilogue fuses
// bias + tanh + V-weighted reduction. One block per 128 rows (never straddles
// a batch boundary since 2048 % 128 == 0).
// ---------------------------------------------------------------------------
__global__ __launch_bounds__(256) void score_kernel(
    const float* __restrict__ values,
    const float* __restrict__ W1,
    const float* __restrict__ b1,
    const float* __restrict__ Vv) {

    __shared__ float As[8][128];
    __shared__ float Bs[8][128];
    __shared__ float red[128][17];

    const int tid  = threadIdx.x;
    const int tx   = tid & 15;      // u direction
    const int ty   = tid >> 4;      // row direction
    const int row0 = blockIdx.x * 128;
    const int b    = row0 >> 11;    // row0 / 2048
    const float* A  = values + (size_t)row0 * DV;
    const float* PQ = g_projq + b * UN;

    const int a_row = tid >> 1;          // 0..127
    const int a_col = (tid & 1) << 2;    // 0 or 4
    const int b_row = tid >> 5;          // 0..7
    const int b_col = (tid & 31) << 2;   // 0..124

    float sp[8];
#pragma unroll
    for (int i = 0; i < 8; ++i) sp[i] = 0.0f;

    for (int ut = 0; ut < 8; ++ut) {
        const float* Bp = W1 + ut * 128;   // column offset u0 = ut*128
        float c[8][8];
#pragma unroll
        for (int i = 0; i < 8; ++i)
#pragma unroll
            for (int j = 0; j < 8; ++j) c[i][j] = 0.0f;

        // prefetch first k-chunk into registers
        float4 aR = *(const float4*)(A  + (size_t)a_row * DV + a_col);
        float4 bR = *(const float4*)(Bp + (size_t)b_row * UN + b_col);

        for (int k0 = 0; k0 < DV; k0 += 8) {
            __syncthreads();   // previous chunk's compute done before overwrite
            As[a_col + 0][a_row] = aR.x;
            As[a_col + 1][a_row] = aR.y;
            As[a_col + 2][a_row] = aR.z;
            As[a_col + 3][a_row] = aR.w;
            *(float4*)(&Bs[b_row][b_col]) = bR;
            __syncthreads();

            if (k0 + 8 < DV) {   // prefetch next chunk, overlap with compute
                aR = *(const float4*)(A  + (size_t)a_row * DV + (k0 + 8) + a_col);
                bR = *(const float4*)(Bp + (size_t)(k0 + 8 + b_row) * UN + b_col);
            }

#pragma unroll
            for (int kk = 0; kk < 8; ++kk) {
                float a[8], bb[8];
#pragma unroll
                for (int i = 0; i < 8; ++i) a[i]  = As[kk][ty + 16 * i];
#pragma unroll
                for (int j = 0; j < 8; ++j) bb[j] = Bs[kk][tx + 16 * j];
#pragma unroll
                for (int i = 0; i < 8; ++i)
#pragma unroll
                    for (int j = 0; j < 8; ++j)
                        c[i][j] = fmaf(a[i], bb[j], c[i][j]);
            }
        }

        // epilogue for this u-tile: bias + tanh + V-weighted reduce
        const int u0 = ut * 128;
#pragma unroll
        for (int j = 0; j < 8; ++j) {
            const int u  = u0 + tx + 16 * j;
            const float bias = b1[u] + PQ[u];
            const float vw   = Vv[u];
#pragma unroll
            for (int i = 0; i < 8; ++i)
                sp[i] = fmaf(fast_tanh(c[i][j] + bias), vw, sp[i]);
        }
    }

    // reduce partial scores across the 16 u-threads per row
    __syncthreads();
#pragma unroll
    for (int i = 0; i < 8; ++i) red[ty + 16 * i][tx] = sp[i];
    __syncthreads();
    if (tid < 128) {
        float s = 0.0f;
#pragma unroll
        for (int x = 0; x < 16; ++x) s += red[tid][x];
        g_score[row0 + tid] = s;   // bV omitted: softmax-invariant
    }
}

// ---------------------------------------------------------------------------
// K3: softmax over S per batch.  grid(32) x 256, 8 elems/thread
// ---------------------------------------------------------------------------
__global__ void softmax_kernel(float* __restrict__ out_w) {
    const int b   = blockIdx.x;
    const int tid = threadIdx.x;
    __shared__ float sm[256];

    float v[8];
    float lmax = -1e30f;
#pragma unroll
    for (int i = 0; i < 8; ++i) {
        v[i] = g_score[b * SEQ + tid + i * 256];
        lmax = fmaxf(lmax, v[i]);
    }
    sm[tid] = lmax;
    __syncthreads();
    for (int s = 128; s > 0; s >>= 1) {
        if (tid < s) sm[tid] = fmaxf(sm[tid], sm[tid + s]);
        __syncthreads();
    }
    const float m = sm[0];
    __syncthreads();

    float lsum = 0.0f;
#pragma unroll
    for (int i = 0; i < 8; ++i) {
        v[i] = __expf(v[i] - m);
        lsum += v[i];
    }
    sm[tid] = lsum;
    __syncthreads();
    for (int s = 128; s > 0; s >>= 1) {
        if (tid < s) sm[tid] += sm[tid + s];
        __syncthreads();
    }
    const float inv = 1.0f / sm[0];
#pragma unroll
    for (int i = 0; i < 8; ++i)
        out_w[b * SEQ + tid + i * 256] = v[i] * inv;
}

// ---------------------------------------------------------------------------
// K4: context[b,d] = sum_s w[b,s] * values[b,s,d].  grid(4, 32) x 256
// Weights staged in smem; values reads fully coalesced.
// ---------------------------------------------------------------------------
__global__ void context_kernel(const float* __restrict__ values,
                               const float* __restrict__ w,
                               float* __restrict__ out_c) {
    __shared__ float ws[SEQ];
    const int d = blockIdx.x * 256 + threadIdx.x;
    const int b = blockIdx.y;

    for (int s = threadIdx.x; s < SEQ; s += 256)
        ws[s] = w[b * SEQ + s];
    __syncthreads();

    const float* vb = values + (size_t)b * SEQ * DV + d;
    float acc = 0.0f;
#pragma unroll 4
    for (int s = 0; s < SEQ; ++s)
        acc = fmaf(ws[s], vb[(size_t)s * DV], acc);
    out_c[b * DV + d] = acc;
}

// ---------------------------------------------------------------------------
extern "C" void kernel_launch(void* const* d_in, const int* in_sizes, int n_in,
                              void* d_out, int out_size) {
    const float* query  = (const float*)d_in[0];
    const float* values = (const float*)d_in[1];
    const float* W1     = (const float*)d_in[2];
    const float* b1     = (const float*)d_in[3];
    const float* W2     = (const float*)d_in[4];
    const float* b2     = (const float*)d_in[5];
    const float* Vv     = (const float*)d_in[6];
    // d_in[7] = bV: uniform shift of scores, cancels in softmax -> unused.

    float* out_c = (float*)d_out;          // context_vector [32, 1024]
    float* out_w = out_c + BATCH * DV;     // attention_weights [32, 2048, 1]

    projq_kernel  <<<dim3(UN / 256, BATCH), 256>>>(query, W2, b2);
    score_kernel  <<<ROWS / 128, 256>>>(values, W1, b1, Vv);
    softmax_kernel<<<BATCH, 256>>>(out_w);
    context_kernel<<<dim3(DV / 256, BATCH), 256>>>(values, out_w, out_c);
}

// round 3
// speedup vs baseline: 2.5217x; 2.5217x over previous
#include <cuda_runtime.h>
#include <cuda_bf16.h>
#include <math.h>
#include <stdint.h>

#define BATCH 32
#define SEQ   2048
#define DQ    1024
#define DV    1024
#define UN    1024
#define ROWS  (BATCH * SEQ)

#define BM 128
#define BN 128
#define BK 64
#define NCHUNK (DV / BK)          // 16
#define BUF_BYTES 65536           // Ah 16K | Al 16K | Bh 16K | Bl 16K
#define SMEM_BYTES (2 * BUF_BYTES)

// ---------------- device scratch (no allocation allowed) -------------------
__device__ __nv_bfloat16 g_vhi[(size_t)ROWS * DV];
__device__ __nv_bfloat16 g_vlo[(size_t)ROWS * DV];
__device__ __nv_bfloat16 g_w1t_hi[(size_t)UN * DV];   // [u][k]
__device__ __nv_bfloat16 g_w1t_lo[(size_t)UN * DV];
__device__ float g_projq[BATCH * UN];
__device__ float g_spart[(size_t)ROWS * 8];           // per-u-tile partial scores
__device__ float g_cpart[16 * BATCH * DV];

// ---------------- helpers ---------------------------------------------------
__device__ __forceinline__ uint32_t smem_u32(const void* p) {
    uint32_t a;
    asm("{ .reg .u64 t; cvta.to.shared.u64 t, %1; cvt.u32.u64 %0, t; }" : "=r"(a) : "l"(p));
    return a;
}
__device__ __forceinline__ void cp_async16(uint32_t s, const void* g) {
    asm volatile("cp.async.cg.shared.global [%0], [%1], 16;" :: "r"(s), "l"(g) : "memory");
}
#define CP_COMMIT() asm volatile("cp.async.commit_group;" ::: "memory")
#define CP_WAIT(n)  asm volatile("cp.async.wait_group %0;" :: "n"(n) : "memory")
#define LDSM_X4(R, addr) \
    asm volatile("ldmatrix.sync.aligned.m8n8.x4.shared.b16 {%0,%1,%2,%3}, [%4];" \
        : "=r"((R)[0]), "=r"((R)[1]), "=r"((R)[2]), "=r"((R)[3]) : "r"(addr))
#define MMA16816(C, A, B0, B1) \
    asm volatile("mma.sync.aligned.m16n8k16.row.col.f32.bf16.bf16.f32 " \
        "{%0,%1,%2,%3},{%4,%5,%6,%7},{%8,%9},{%0,%1,%2,%3};" \
        : "+f"((C)[0]), "+f"((C)[1]), "+f"((C)[2]), "+f"((C)[3]) \
        : "r"((A)[0]), "r"((A)[1]), "r"((A)[2]), "r"((A)[3]), "r"(B0), "r"(B1))
#define SWZ128(o) ((o) ^ (((o) >> 3) & 0x70))

// MUFU-free tanh: exp2 range-reduction (magic const) + deg-5 poly + bit-trick
// reciprocal with 3 Newton steps. abs err ~2e-6. All FMA/ALU pipe.
__device__ __forceinline__ float tanh_fma(float x) {
    float ax = fabsf(x);
    float y  = fminf(ax * 2.885390082f, 24.0f);      // 2x*log2(e), clamped
    float r  = y + 12582912.0f;                      // 1.5*2^23: round to int
    int   ki = __float_as_int(r) - 0x4B400000;
    float f  = y - (r - 12582912.0f);                // f in [-0.5, 0.5]
    float p  = 1.33218890e-3f;                       // 2^f Taylor deg-5
    p = fmaf(p, f, 9.61812910e-3f);
    p = fmaf(p, f, 5.55041087e-2f);
    p = fmaf(p, f, 2.40226507e-1f);
    p = fmaf(p, f, 6.93147181e-1f);
    p = fmaf(p, f, 1.0f);
    float e   = __int_as_float(__float_as_int(p) + (ki << 23));   // e^{2ax}
    float den = e + 1.0f;
    float z   = __int_as_float(0x7EF311C3 - __float_as_int(den)); // ~1/den
    z = z * fmaf(-den, z, 2.0f);
    z = z * fmaf(-den, z, 2.0f);
    z = z * fmaf(-den, z, 2.0f);
    float t = fmaf(-2.0f, z, 1.0f);                  // tanh(ax)
    return copysignf(t, x);
}

// ---------------------------------------------------------------------------
// prep A: split values fp32 -> hi/lo bf16
// ---------------------------------------------------------------------------
__global__ void split_values_kernel(const float* __restrict__ v) {
    size_t i = ((size_t)blockIdx.x * 256 + threadIdx.x) * 4;
    float4 x = *(const float4*)(v + i);
    __nv_bfloat16 h0 = __float2bfloat16_rn(x.x);
    __nv_bfloat16 h1 = __float2bfloat16_rn(x.y);
    __nv_bfloat16 h2 = __float2bfloat16_rn(x.z);
    __nv_bfloat16 h3 = __float2bfloat16_rn(x.w);
    __nv_bfloat16 l0 = __float2bfloat16_rn(x.x - __bfloat162float(h0));
    __nv_bfloat16 l1 = __float2bfloat16_rn(x.y - __bfloat162float(h1));
    __nv_bfloat16 l2 = __float2bfloat16_rn(x.z - __bfloat162float(h2));
    __nv_bfloat16 l3 = __float2bfloat16_rn(x.w - __bfloat162float(h3));
    *(__nv_bfloat162*)(g_vhi + i)     = __nv_bfloat162(h0, h1);
    *(__nv_bfloat162*)(g_vhi + i + 2) = __nv_bfloat162(h2, h3);
    *(__nv_bfloat162*)(g_vlo + i)     = __nv_bfloat162(l0, l1);
    *(__nv_bfloat162*)(g_vlo + i + 2) = __nv_bfloat162(l2, l3);
}

// ---------------------------------------------------------------------------
// prep B: W1 [k][u] -> W1^T hi/lo bf16 [u][k]
// ---------------------------------------------------------------------------
__global__ void split_w1t_kernel(const float* __restrict__ W1) {
    __shared__ float t[32][33];
    const int bx = blockIdx.x * 32, by = blockIdx.y * 32;
    const int tx = threadIdx.x, ty = threadIdx.y;
#pragma unroll
    for (int r = 0; r < 4; ++r)
        t[ty + 8 * r][tx] = W1[(size_t)(by + ty + 8 * r) * UN + bx + tx];
    __syncthreads();
#pragma unroll
    for (int r = 0; r < 4; ++r) {
        float x = t[tx][ty + 8 * r];
        __nv_bfloat16 h = __float2bfloat16_rn(x);
        __nv_bfloat16 l = __float2bfloat16_rn(x - __bfloat162float(h));
        size_t o = (size_t)(bx + ty + 8 * r) * DV + by + tx;
        g_w1t_hi[o] = h;
        g_w1t_lo[o] = l;
    }
}

// ---------------------------------------------------------------------------
// proj_q
// ---------------------------------------------------------------------------
__global__ void projq_kernel(const float* __restrict__ q,
                             const float* __restrict__ W2,
                             const float* __restrict__ b2) {
    const int u = blockIdx.x * 256 + threadIdx.x;
    const int b = blockIdx.y;
    const float* qb = q + b * DQ;
    float acc = b2[u];
#pragma unroll 8
    for (int d = 0; d < DQ; ++d)
        acc = fmaf(qb[d], W2[(size_t)d * UN + u], acc);
    g_projq[b * UN + u] = acc;
}

// ---------------------------------------------------------------------------
// score: mma.sync bf16x3 GEMM, fused bias+tanh+V epilogue.
// grid(8 u-tiles, 512 row-tiles) x 256 threads.
// ---------------------------------------------------------------------------
__global__ __launch_bounds__(256, 1) void score_kernel(
    const float* __restrict__ b1g, const float* __restrict__ Vv) {

    extern __shared__ char smem[];
    const uint32_t sb = smem_u32(smem);
    const int tid = threadIdx.x, wid = tid >> 5, lane = tid & 31;
    const int u0   = blockIdx.x * BN;
    const int row0 = blockIdx.y * BM;
    const int b    = row0 >> 11;
    const int warp_m = wid & 1, warp_n = wid >> 1;

    // cp.async mapping: thread -> (row, 4 consecutive 16B chunks)
    const int ld_row = tid >> 1;
    const int ld_c0  = (tid & 1) * 4;
    const size_t a_g0 = (size_t)(row0 + ld_row) * DV + ld_c0 * 8;
    const size_t b_g0 = (size_t)(u0   + ld_row) * DV + ld_c0 * 8;
    const uint32_t ld_sm = ld_row * 128;

    // ldmatrix per-thread bases
    const int lr = lane & 15, lh = lane >> 4;
    uint32_t a_base[4], b_base[2];
    int a_xor[4], b_xor[2];
#pragma unroll
    for (int mt = 0; mt < 4; ++mt) {
        int r = warp_m * 64 + mt * 16 + lr;
        a_base[mt] = r * 128; a_xor[mt] = r & 7;
    }
#pragma unroll
    for (int bt = 0; bt < 2; ++bt) {
        int r = warp_n * 32 + bt * 16 + lr;
        b_base[bt] = r * 128; b_xor[bt] = r & 7;
    }

    float acc[4][4][4];
#pragma unroll
    for (int i = 0; i < 4; ++i)
#pragma unroll
        for (int j = 0; j < 4; ++j)
#pragma unroll
            for (int k = 0; k < 4; ++k) acc[i][j][k] = 0.0f;

    // chunk loader
    auto load_chunk = [&](int s) {
        const uint32_t SB = sb + (s & 1) * BUF_BYTES;
        const int k0 = s * BK;
#pragma unroll
        for (int c = 0; c < 4; ++c) {
            const uint32_t so = SWZ128(ld_sm + (ld_c0 + c) * 16);
            cp_async16(SB + so,         g_vhi    + a_g0 + k0 + c * 8);
            cp_async16(SB + 16384 + so, g_vlo    + a_g0 + k0 + c * 8);
            cp_async16(SB + 32768 + so, g_w1t_hi + b_g0 + k0 + c * 8);
            cp_async16(SB + 49152 + so, g_w1t_lo + b_g0 + k0 + c * 8);
        }
        CP_COMMIT();
    };

    load_chunk(0);
    for (int s = 0; s < NCHUNK; ++s) {
        if (s + 1 < NCHUNK) { load_chunk(s + 1); CP_WAIT(1); }
        else                { CP_WAIT(0); }
        __syncthreads();
        const uint32_t SB = sb + (s & 1) * BUF_BYTES;
#pragma unroll
        for (int ks = 0; ks < 4; ++ks) {
            const int ch = ks * 2 + lh;
            uint32_t a[4][4], bh[2][4], bl[2][4];
#pragma unroll
            for (int mt = 0; mt < 4; ++mt)
                LDSM_X4(a[mt], SB + a_base[mt] + (uint32_t)((ch ^ a_xor[mt]) << 4));
#pragma unroll
            for (int bt = 0; bt < 2; ++bt) {
                const uint32_t off = b_base[bt] + (uint32_t)((ch ^ b_xor[bt]) << 4);
                LDSM_X4(bh[bt], SB + 32768 + off);
                LDSM_X4(bl[bt], SB + 49152 + off);
            }
            // pass0: Ah*Bh, pass1: Ah*Bl
#pragma unroll
            for (int mt = 0; mt < 4; ++mt)
#pragma unroll
                for (int nt = 0; nt < 4; ++nt) {
                    MMA16816(acc[mt][nt], a[mt],
                             bh[nt >> 1][nt & 1], bh[nt >> 1][(nt & 1) + 2]);
                    MMA16816(acc[mt][nt], a[mt],
                             bl[nt >> 1][nt & 1], bl[nt >> 1][(nt & 1) + 2]);
                }
            // pass2: Al*Bh (reuse a regs)
#pragma unroll
            for (int mt = 0; mt < 4; ++mt)
                LDSM_X4(a[mt], SB + 16384 + a_base[mt] + (uint32_t)((ch ^ a_xor[mt]) << 4));
#pragma unroll
            for (int mt = 0; mt < 4; ++mt)
#pragma unroll
                for (int nt = 0; nt < 4; ++nt)
                    MMA16816(acc[mt][nt], a[mt],
                             bh[nt >> 1][nt & 1], bh[nt >> 1][(nt & 1) + 2]);
        }
        __syncthreads();
    }

    // ---------------- fused epilogue ----------------------------------------
    float tb[8], tv[8];
#pragma unroll
    for (int nt = 0; nt < 4; ++nt)
#pragma unroll
        for (int par = 0; par < 2; ++par) {
            const int ul = warp_n * 32 + nt * 8 + (lane & 3) * 2 + par;
            const int u  = u0 + ul;
            tb[nt * 2 + par] = b1g[u] + g_projq[b * UN + u];
            tv[nt * 2 + par] = Vv[u];
        }

    float* red = (float*)smem;   // [128][4] — aliases buffer0 (last chunk used buffer1)
#pragma unroll
    for (int mt = 0; mt < 4; ++mt) {
        float s0 = 0.0f, s1 = 0.0f;
#pragma unroll
        for (int nt = 0; nt < 4; ++nt)
#pragma unroll
            for (int par = 0; par < 2; ++par) {
                const int j = nt * 2 + par;
                s0 = fmaf(tanh_fma(acc[mt][nt][par]     + tb[j]), tv[j], s0);
                s1 = fmaf(tanh_fma(acc[mt][nt][2 + par] + tb[j]), tv[j], s1);
            }
        s0 += __shfl_xor_sync(0xffffffff, s0, 1);
        s0 += __shfl_xor_sync(0xffffffff, s0, 2);
        s1 += __shfl_xor_sync(0xffffffff, s1, 1);
        s1 += __shfl_xor_sync(0xffffffff, s1, 2);
        if ((lane & 3) == 0) {
            const int r = warp_m * 64 + mt * 16 + (lane >> 2);
            red[r * 4 + warp_n]       = s0;
            red[(r + 8) * 4 + warp_n] = s1;
        }
    }
    __syncthreads();
    if (tid < 128) {
        const float s = (red[tid * 4 + 0] + red[tid * 4 + 1]) +
                        (red[tid * 4 + 2] + red[tid * 4 + 3]);
        g_spart[(size_t)(row0 + tid) * 8 + blockIdx.x] = s;
    }
}

// ---------------------------------------------------------------------------
// softmax over S per batch (8-way deterministic partial sum)
// ---------------------------------------------------------------------------
__global__ void softmax_kernel(float* __restrict__ out_w) {
    const int b = blockIdx.x, tid = threadIdx.x;
    __shared__ float sm[256];
    float v[8];
    float lmax = -1e30f;
#pragma unroll
    for (int i = 0; i < 8; ++i) {
        const float* p = g_spart + (size_t)(b * SEQ + tid + i * 256) * 8;
        v[i] = ((p[0] + p[1]) + (p[2] + p[3])) + ((p[4] + p[5]) + (p[6] + p[7]));
        lmax = fmaxf(lmax, v[i]);
    }
    sm[tid] = lmax; __syncthreads();
    for (int s = 128; s > 0; s >>= 1) {
        if (tid < s) sm[tid] = fmaxf(sm[tid], sm[tid + s]);
        __syncthreads();
    }
    const float m = sm[0]; __syncthreads();
    float lsum = 0.0f;
#pragma unroll
    for (int i = 0; i < 8; ++i) { v[i] = __expf(v[i] - m); lsum += v[i]; }
    sm[tid] = lsum; __syncthreads();
    for (int s = 128; s > 0; s >>= 1) {
        if (tid < s) sm[tid] += sm[tid + s];
        __syncthreads();
    }
    const float inv = 1.0f / sm[0];
#pragma unroll
    for (int i = 0; i < 8; ++i)
        out_w[b * SEQ + tid + i * 256] = v[i] * inv;
}

// ---------------------------------------------------------------------------
// context: partial over s-chunks then deterministic reduce
// ---------------------------------------------------------------------------
__global__ void ctx_part_kernel(const float* __restrict__ values,
                                const float* __restrict__ w) {
    __shared__ float ws[128];
    const int sc = blockIdx.x, b = blockIdx.y, tid = threadIdx.x;
    if (tid < 128) ws[tid] = w[b * SEQ + sc * 128 + tid];
    __syncthreads();
    const int d0 = tid * 4;
    const float* base = values + (size_t)b * SEQ * DV + (size_t)sc * 128 * DV + d0;
    float4 acc = make_float4(0.f, 0.f, 0.f, 0.f);
#pragma unroll 4
    for (int s = 0; s < 128; ++s) {
        const float4 v = *(const float4*)(base + (size_t)s * DV);
        const float x = ws[s];
        acc.x = fmaf(x, v.x, acc.x); acc.y = fmaf(x, v.y, acc.y);
        acc.z = fmaf(x, v.z, acc.z); acc.w = fmaf(x, v.w, acc.w);
    }
    *(float4*)(g_cpart + (size_t)(sc * 32 + b) * 1024 + d0) = acc;
}

__global__ void ctx_reduce_kernel(float* __restrict__ out_c) {
    const int idx = blockIdx.x * 256 + threadIdx.x;
    const int bb = idx >> 10, dd = idx & 1023;
    float s = 0.0f;
#pragma unroll
    for (int c = 0; c < 16; ++c)
        s += g_cpart[(size_t)(c * 32 + bb) * 1024 + dd];
    out_c[idx] = s;
}

// ---------------------------------------------------------------------------
extern "C" void kernel_launch(void* const* d_in, const int* in_sizes, int n_in,
                              void* d_out, int out_size) {
    const float* query  = (const float*)d_in[0];
    const float* values = (const float*)d_in[1];
    const float* W1     = (const float*)d_in[2];
    const float* b1     = (const float*)d_in[3];
    const float* W2     = (const float*)d_in[4];
    const float* b2     = (const float*)d_in[5];
    const float* Vv     = (const float*)d_in[6];
    // d_in[7] = bV: cancels in softmax.

    float* out_c = (float*)d_out;
    float* out_w = out_c + BATCH * DV;

    static bool attr_set = false;
    if (!attr_set) {
        cudaFuncSetAttribute(score_kernel,
                             cudaFuncAttributeMaxDynamicSharedMemorySize, SMEM_BYTES);
        attr_set = true;
    }

    split_values_kernel<<<65536, 256>>>(values);
    split_w1t_kernel<<<dim3(32, 32), dim3(32, 8)>>>(W1);
    projq_kernel<<<dim3(4, BATCH), 256>>>(query, W2, b2);
    score_kernel<<<dim3(8, 512), 256, SMEM_BYTES>>>(b1, Vv);
    softmax_kernel<<<BATCH, 256>>>(out_w);
    ctx_part_kernel<<<dim3(16, BATCH), 256>>>(values, out_w);
    ctx_reduce_kernel<<<128, 256>>>(out_c);
}

// round 4
// speedup vs baseline: 2.8164x; 1.1168x over previous
#include <cuda_runtime.h>
#include <cuda_bf16.h>
#include <math.h>
#include <stdint.h>

#define BATCH 32
#define SEQ   2048
#define DQ    1024
#define DV    1024
#define UN    1024
#define ROWS  (BATCH * SEQ)

#define BM 128
#define BN 128
#define BK 32
#define NCHUNK (DV / BK)            // 32
#define STAGE_BYTES 32768           // Ah 8K | Al 8K | Bh 8K | Bl 8K
#define NSTAGE 3
#define SMEM_BYTES (NSTAGE * STAGE_BYTES)   // 96 KB
#define NCTX 64                     // context s-chunks

// ---------------- device scratch (no allocation allowed) -------------------
__device__ __nv_bfloat16 g_vhi[(size_t)ROWS * DV];
__device__ __nv_bfloat16 g_vlo[(size_t)ROWS * DV];
__device__ __nv_bfloat16 g_w1t_hi[(size_t)UN * DV];   // [u][k]
__device__ __nv_bfloat16 g_w1t_lo[(size_t)UN * DV];
__device__ float g_projq[BATCH * UN];
__device__ float g_spart[(size_t)ROWS * 8];
__device__ float g_cpart[(size_t)NCTX * BATCH * DV];

// ---------------- helpers ---------------------------------------------------
__device__ __forceinline__ uint32_t smem_u32(const void* p) {
    uint32_t a;
    asm("{ .reg .u64 t; cvta.to.shared.u64 t, %1; cvt.u32.u64 %0, t; }" : "=r"(a) : "l"(p));
    return a;
}
__device__ __forceinline__ void cp_async16(uint32_t s, const void* g) {
    asm volatile("cp.async.cg.shared.global [%0], [%1], 16;" :: "r"(s), "l"(g) : "memory");
}
#define CP_COMMIT() asm volatile("cp.async.commit_group;" ::: "memory")
#define CP_WAIT(n)  asm volatile("cp.async.wait_group %0;" :: "n"(n) : "memory")
#define LDSM_X4(R, addr) \
    asm volatile("ldmatrix.sync.aligned.m8n8.x4.shared.b16 {%0,%1,%2,%3}, [%4];" \
        : "=r"((R)[0]), "=r"((R)[1]), "=r"((R)[2]), "=r"((R)[3]) : "r"(addr))
#define MMA16816(C, A, B0, B1) \
    asm volatile("mma.sync.aligned.m16n8k16.row.col.f32.bf16.bf16.f32 " \
        "{%0,%1,%2,%3},{%4,%5,%6,%7},{%8,%9},{%0,%1,%2,%3};" \
        : "+f"((C)[0]), "+f"((C)[1]), "+f"((C)[2]), "+f"((C)[3]) \
        : "r"((A)[0]), "r"((A)[1]), "r"((A)[2]), "r"((A)[3]), "r"(B0), "r"(B1))

// SW64 swizzle helpers: 64B rows, chunk index c (0..3) of row r maps to c^((r>>1)&3)
__device__ __forceinline__ uint32_t sw64_off(int row, int c) {
    return (uint32_t)(row * 64 + ((c ^ ((row >> 1) & 3)) << 4));
}

// MUFU-free tanh (FMA/ALU only), abs err ~2e-6
__device__ __forceinline__ float tanh_fma(float x) {
    float ax = fabsf(x);
    float y  = fminf(ax * 2.885390082f, 24.0f);
    float r  = y + 12582912.0f;
    int   ki = __float_as_int(r) - 0x4B400000;
    float f  = y - (r - 12582912.0f);
    float p  = 1.33218890e-3f;
    p = fmaf(p, f, 9.61812910e-3f);
    p = fmaf(p, f, 5.55041087e-2f);
    p = fmaf(p, f, 2.40226507e-1f);
    p = fmaf(p, f, 6.93147181e-1f);
    p = fmaf(p, f, 1.0f);
    float e   = __int_as_float(__float_as_int(p) + (ki << 23));
    float den = e + 1.0f;
    float z   = __int_as_float(0x7EF311C3 - __float_as_int(den));
    z = z * fmaf(-den, z, 2.0f);
    z = z * fmaf(-den, z, 2.0f);
    z = z * fmaf(-den, z, 2.0f);
    float t = fmaf(-2.0f, z, 1.0f);
    return copysignf(t, x);
}

// ---------------------------------------------------------------------------
__global__ void split_values_kernel(const float* __restrict__ v) {
    size_t i = ((size_t)blockIdx.x * 256 + threadIdx.x) * 4;
    float4 x = *(const float4*)(v + i);
    __nv_bfloat16 h0 = __float2bfloat16_rn(x.x);
    __nv_bfloat16 h1 = __float2bfloat16_rn(x.y);
    __nv_bfloat16 h2 = __float2bfloat16_rn(x.z);
    __nv_bfloat16 h3 = __float2bfloat16_rn(x.w);
    __nv_bfloat16 l0 = __float2bfloat16_rn(x.x - __bfloat162float(h0));
    __nv_bfloat16 l1 = __float2bfloat16_rn(x.y - __bfloat162float(h1));
    __nv_bfloat16 l2 = __float2bfloat16_rn(x.z - __bfloat162float(h2));
    __nv_bfloat16 l3 = __float2bfloat16_rn(x.w - __bfloat162float(h3));
    *(__nv_bfloat162*)(g_vhi + i)     = __nv_bfloat162(h0, h1);
    *(__nv_bfloat162*)(g_vhi + i + 2) = __nv_bfloat162(h2, h3);
    *(__nv_bfloat162*)(g_vlo + i)     = __nv_bfloat162(l0, l1);
    *(__nv_bfloat162*)(g_vlo + i + 2) = __nv_bfloat162(l2, l3);
}

__global__ void split_w1t_kernel(const float* __restrict__ W1) {
    __shared__ float t[32][33];
    const int bx = blockIdx.x * 32, by = blockIdx.y * 32;
    const int tx = threadIdx.x, ty = threadIdx.y;
#pragma unroll
    for (int r = 0; r < 4; ++r)
        t[ty + 8 * r][tx] = W1[(size_t)(by + ty + 8 * r) * UN + bx + tx];
    __syncthreads();
#pragma unroll
    for (int r = 0; r < 4; ++r) {
        float x = t[tx][ty + 8 * r];
        __nv_bfloat16 h = __float2bfloat16_rn(x);
        __nv_bfloat16 l = __float2bfloat16_rn(x - __bfloat162float(h));
        size_t o = (size_t)(bx + ty + 8 * r) * DV + by + tx;
        g_w1t_hi[o] = h;
        g_w1t_lo[o] = l;
    }
}

__global__ void projq_kernel(const float* __restrict__ q,
                             const float* __restrict__ W2,
                             const float* __restrict__ b2) {
    const int u = blockIdx.x * 256 + threadIdx.x;
    const int b = blockIdx.y;
    const float* qb = q + b * DQ;
    float acc = b2[u];
#pragma unroll 8
    for (int d = 0; d < DQ; ++d)
        acc = fmaf(qb[d], W2[(size_t)d * UN + u], acc);
    g_projq[b * UN + u] = acc;
}

// ---------------------------------------------------------------------------
// score: bf16x3 HMMA GEMM, 3-stage cp.async pipeline, 2 CTAs/SM.
// grid(8 u-tiles, 512 row-tiles) x 256 threads.
// ---------------------------------------------------------------------------
__global__ __launch_bounds__(256, 2) void score_kernel(
    const float* __restrict__ b1g, const float* __restrict__ Vv) {

    extern __shared__ char smem[];
    const uint32_t sb = smem_u32(smem);
    const int tid = threadIdx.x, wid = tid >> 5, lane = tid & 31;
    const int u0   = blockIdx.x * BN;
    const int row0 = blockIdx.y * BM;
    const int b    = row0 >> 11;
    const int warp_m = wid & 1, warp_n = wid >> 1;

    // ---- producer setup: thread -> (row, 2 x 16B chunks) -------------------
    const int prow = tid >> 1;
    const int pc0  = (tid & 1) * 2;
    const uint32_t so0 = sw64_off(prow, pc0);
    const uint32_t so1 = so0 ^ 16;                    // chunk pc0+1
    const __nv_bfloat16* pAh = g_vhi    + (size_t)(row0 + prow) * DV + pc0 * 8;
    const __nv_bfloat16* pAl = g_vlo    + (size_t)(row0 + prow) * DV + pc0 * 8;
    const __nv_bfloat16* pBh = g_w1t_hi + (size_t)(u0   + prow) * DV + pc0 * 8;
    const __nv_bfloat16* pBl = g_w1t_lo + (size_t)(u0   + prow) * DV + pc0 * 8;

    // ---- ldmatrix setup ----------------------------------------------------
    const int lr = lane & 15, lh = lane >> 4;
    uint32_t aoff[4], boff[2];
#pragma unroll
    for (int mt = 0; mt < 4; ++mt)
        aoff[mt] = sw64_off(warp_m * 64 + mt * 16 + lr, lh);
#pragma unroll
    for (int bt = 0; bt < 2; ++bt)
        boff[bt] = sw64_off(warp_n * 32 + bt * 16 + lr, lh);

    float acc[4][4][4];
#pragma unroll
    for (int i = 0; i < 4; ++i)
#pragma unroll
        for (int j = 0; j < 4; ++j)
#pragma unroll
            for (int k = 0; k < 4; ++k) acc[i][j][k] = 0.0f;

    uint32_t sb_ld = sb;                   // next stage to fill
    int k_ld = 0;                          // element offset of next chunk
#define LOAD_CHUNK() do { \
        cp_async16(sb_ld + so0,          pAh + k_ld);     \
        cp_async16(sb_ld + so1,          pAh + k_ld + 8); \
        cp_async16(sb_ld + 8192  + so0,  pAl + k_ld);     \
        cp_async16(sb_ld + 8192  + so1,  pAl + k_ld + 8); \
        cp_async16(sb_ld + 16384 + so0,  pBh + k_ld);     \
        cp_async16(sb_ld + 16384 + so1,  pBh + k_ld + 8); \
        cp_async16(sb_ld + 24576 + so0,  pBl + k_ld);     \
        cp_async16(sb_ld + 24576 + so1,  pBl + k_ld + 8); \
        CP_COMMIT(); \
        k_ld += BK; \
        sb_ld += STAGE_BYTES; \
        if (sb_ld == sb + SMEM_BYTES) sb_ld = sb; \
    } while (0)

    LOAD_CHUNK();
    LOAD_CHUNK();

    uint32_t sb_cp = sb;                   // stage to compute
    for (int s = 0; s < NCHUNK; ++s) {
        CP_WAIT(1);
        __syncthreads();
        if (s + 2 < NCHUNK) { LOAD_CHUNK(); } else { CP_COMMIT(); }

#pragma unroll
        for (int ks = 0; ks < 2; ++ks) {
            const uint32_t kx = ks << 5;    // XOR 32 selects second 16B pair
            uint32_t a[4][4], bh[2][4], bl[2][4];
#pragma unroll
            for (int mt = 0; mt < 4; ++mt)
                LDSM_X4(a[mt], sb_cp + (aoff[mt] ^ kx));
#pragma unroll
            for (int bt = 0; bt < 2; ++bt) {
                LDSM_X4(bh[bt], sb_cp + 16384 + (boff[bt] ^ kx));
                LDSM_X4(bl[bt], sb_cp + 24576 + (boff[bt] ^ kx));
            }
#pragma unroll
            for (int mt = 0; mt < 4; ++mt)
#pragma unroll
                for (int nt = 0; nt < 4; ++nt) {
                    MMA16816(acc[mt][nt], a[mt],
                             bh[nt >> 1][nt & 1], bh[nt >> 1][(nt & 1) + 2]);
                    MMA16816(acc[mt][nt], a[mt],
                             bl[nt >> 1][nt & 1], bl[nt >> 1][(nt & 1) + 2]);
                }
#pragma unroll
            for (int mt = 0; mt < 4; ++mt)
                LDSM_X4(a[mt], sb_cp + 8192 + (aoff[mt] ^ kx));
#pragma unroll
            for (int mt = 0; mt < 4; ++mt)
#pragma unroll
                for (int nt = 0; nt < 4; ++nt)
                    MMA16816(acc[mt][nt], a[mt],
                             bh[nt >> 1][nt & 1], bh[nt >> 1][(nt & 1) + 2]);
        }
        sb_cp += STAGE_BYTES;
        if (sb_cp == sb + SMEM_BYTES) sb_cp = sb;
    }

    // ---------------- fused epilogue ----------------------------------------
    float tb[8], tv[8];
#pragma unroll
    for (int nt = 0; nt < 4; ++nt)
#pragma unroll
        for (int par = 0; par < 2; ++par) {
            const int u = u0 + warp_n * 32 + nt * 8 + (lane & 3) * 2 + par;
            tb[nt * 2 + par] = b1g[u] + g_projq[b * UN + u];
            tv[nt * 2 + par] = Vv[u];
        }

    float* red = (float*)smem;   // stage 0 region; safe (last compute = stage 2)
#pragma unroll
    for (int mt = 0; mt < 4; ++mt) {
        float s0 = 0.0f, s1 = 0.0f;
#pragma unroll
        for (int nt = 0; nt < 4; ++nt)
#pragma unroll
            for (int par = 0; par < 2; ++par) {
                const int j = nt * 2 + par;
                s0 = fmaf(tanh_fma(acc[mt][nt][par]     + tb[j]), tv[j], s0);
                s1 = fmaf(tanh_fma(acc[mt][nt][2 + par] + tb[j]), tv[j], s1);
            }
        s0 += __shfl_xor_sync(0xffffffff, s0, 1);
        s0 += __shfl_xor_sync(0xffffffff, s0, 2);
        s1 += __shfl_xor_sync(0xffffffff, s1, 1);
        s1 += __shfl_xor_sync(0xffffffff, s1, 2);
        if ((lane & 3) == 0) {
            const int r = warp_m * 64 + mt * 16 + (lane >> 2);
            red[r * 4 + warp_n]       = s0;
            red[(r + 8) * 4 + warp_n] = s1;
        }
    }
    __syncthreads();
    if (tid < 128) {
        const float s = (red[tid * 4 + 0] + red[tid * 4 + 1]) +
                        (red[tid * 4 + 2] + red[tid * 4 + 3]);
        g_spart[(size_t)(row0 + tid) * 8 + blockIdx.x] = s;
    }
}

// ---------------------------------------------------------------------------
__global__ void softmax_kernel(float* __restrict__ out_w) {
    const int b = blockIdx.x, tid = threadIdx.x;
    __shared__ float sm[256];
    float v[8];
    float lmax = -1e30f;
#pragma unroll
    for (int i = 0; i < 8; ++i) {
        const float* p = g_spart + (size_t)(b * SEQ + tid + i * 256) * 8;
        v[i] = ((p[0] + p[1]) + (p[2] + p[3])) + ((p[4] + p[5]) + (p[6] + p[7]));
        lmax = fmaxf(lmax, v[i]);
    }
    sm[tid] = lmax; __syncthreads();
    for (int s = 128; s > 0; s >>= 1) {
        if (tid < s) sm[tid] = fmaxf(sm[tid], sm[tid + s]);
        __syncthreads();
    }
    const float m = sm[0]; __syncthreads();
    float lsum = 0.0f;
#pragma unroll
    for (int i = 0; i < 8; ++i) { v[i] = __expf(v[i] - m); lsum += v[i]; }
    sm[tid] = lsum; __syncthreads();
    for (int s = 128; s > 0; s >>= 1) {
        if (tid < s) sm[tid] += sm[tid + s];
        __syncthreads();
    }
    const float inv = 1.0f / sm[0];
#pragma unroll
    for (int i = 0; i < 8; ++i)
        out_w[b * SEQ + tid + i * 256] = v[i] * inv;
}

// ---------------------------------------------------------------------------
// context: 64 s-chunks of 32 rows -> 2048 CTAs, then 64-way reduce
// ---------------------------------------------------------------------------
__global__ void ctx_part_kernel(const float* __restrict__ values,
                                const float* __restrict__ w) {
    __shared__ float ws[32];
    const int sc = blockIdx.x, b = blockIdx.y, tid = threadIdx.x;
    if (tid < 32) ws[tid] = w[b * SEQ + sc * 32 + tid];
    __syncthreads();
    const int d0 = tid * 4;
    const float* base = values + (size_t)b * SEQ * DV + (size_t)sc * 32 * DV + d0;
    float4 acc = make_float4(0.f, 0.f, 0.f, 0.f);
#pragma unroll 8
    for (int s = 0; s < 32; ++s) {
        const float4 v = *(const float4*)(base + (size_t)s * DV);
        const float x = ws[s];
        acc.x = fmaf(x, v.x, acc.x); acc.y = fmaf(x, v.y, acc.y);
        acc.z = fmaf(x, v.z, acc.z); acc.w = fmaf(x, v.w, acc.w);
    }
    *(float4*)(g_cpart + (size_t)(sc * BATCH + b) * DV + d0) = acc;
}

__global__ void ctx_reduce_kernel(float* __restrict__ out_c) {
    const int idx = blockIdx.x * 256 + threadIdx.x;   // b*1024 + d
    const int bb = idx >> 10, dd = idx & 1023;
    float s = 0.0f;
#pragma unroll 8
    for (int c = 0; c < NCTX; ++c)
        s += g_cpart[(size_t)(c * BATCH + bb) * DV + dd];
    out_c[idx] = s;
}

// ---------------------------------------------------------------------------
extern "C" void kernel_launch(void* const* d_in, const int* in_sizes, int n_in,
                              void* d_out, int out_size) {
    const float* query  = (const float*)d_in[0];
    const float* values = (const float*)d_in[1];
    const float* W1     = (const float*)d_in[2];
    const float* b1     = (const float*)d_in[3];
    const float* W2     = (const float*)d_in[4];
    const float* b2     = (const float*)d_in[5];
    const float* Vv     = (const float*)d_in[6];
    // d_in[7] = bV: cancels in softmax.

    float* out_c = (float*)d_out;
    float* out_w = out_c + BATCH * DV;

    static bool attr_set = false;
    if (!attr_set) {
        cudaFuncSetAttribute(score_kernel,
                             cudaFuncAttributeMaxDynamicSharedMemorySize, SMEM_BYTES);
        attr_set = true;
    }

    split_values_kernel<<<65536, 256>>>(values);
    split_w1t_kernel<<<dim3(32, 32), dim3(32, 8)>>>(W1);
    projq_kernel<<<dim3(4, BATCH), 256>>>(query, W2, b2);
    score_kernel<<<dim3(8, 512), 256, SMEM_BYTES>>>(b1, Vv);
    softmax_kernel<<<BATCH, 256>>>(out_w);
    ctx_part_kernel<<<dim3(NCTX, BATCH), 256>>>(values, out_w);
    ctx_reduce_kernel<<<128, 256>>>(out_c);
}

// round 5
// speedup vs baseline: 3.6359x; 1.2910x over previous
#include <cuda_runtime.h>
#include <cuda_bf16.h>
#include <math.h>
#include <stdint.h>

#define BATCH 32
#define SEQ   2048
#define DQ    1024
#define DV    1024
#define UN    1024
#define ROWS  (BATCH * SEQ)

#define BM 128
#define BN 128
#define BK 32
#define NCHUNK (DV / BK)              // 32
#define CHUNK_BYTES 16384             // per-operand per chunk (hi 8K + lo 8K)
#define STAGE_BYTES 32768             // A 16K + B 16K
#define NSTAGE 3
#define SMEM_BYTES (1024 + NSTAGE * STAGE_BYTES)
#define NCTX 64

// ---------------- device scratch ------------------------------------------
// Tiled, pre-swizzled operand storage: one linear 16KB bulk copy per operand
// per chunk lands the exact smem image ldmatrix expects.
__device__ unsigned char g_at[(size_t)(ROWS / BM) * NCHUNK * CHUNK_BYTES]; // 256MB
__device__ unsigned char g_bt[(size_t)(UN / BN) * NCHUNK * CHUNK_BYTES];   // 4MB
__device__ float g_projq[BATCH * UN];
__device__ float g_spart[(size_t)ROWS * 8];
__device__ float g_cpart[(size_t)NCTX * BATCH * DV];

// ---------------- helpers ---------------------------------------------------
__device__ __forceinline__ uint32_t smem_u32(const void* p) {
    uint32_t a;
    asm("{ .reg .u64 t; cvta.to.shared.u64 t, %1; cvt.u32.u64 %0, t; }" : "=r"(a) : "l"(p));
    return a;
}
#define MBARRIER_INIT(addr, cnt) \
    asm volatile("mbarrier.init.shared.b64 [%0], %1;" :: "r"((uint32_t)(addr)), "r"((uint32_t)(cnt)) : "memory")
#define MBARRIER_ARRIVE(addr) \
    asm volatile("mbarrier.arrive.shared.b64 _, [%0];" :: "r"((uint32_t)(addr)) : "memory")
#define MBARRIER_EXPECT_TX(addr, tx) \
    asm volatile("mbarrier.arrive.expect_tx.shared.b64 _, [%0], %1;" :: "r"((uint32_t)(addr)), "r"((uint32_t)(tx)) : "memory")
#define MBARRIER_WAIT(addr, ph) do { \
    uint32_t _m = (uint32_t)(addr), _p = (uint32_t)(ph), _d; \
    asm volatile("{\n\t.reg .pred p;\n\t" \
        "mbarrier.try_wait.parity.acquire.cta.shared::cta.b64 p, [%1], %2;\n\t" \
        "selp.b32 %0, 1, 0, p;\n\t}" : "=r"(_d) : "r"(_m), "r"(_p) : "memory"); \
    if (!_d) { \
        asm volatile("{\n\t.reg .pred P1;\n\t" \
            "WL_%=:\n\t" \
            "mbarrier.try_wait.parity.acquire.cta.shared::cta.b64 P1, [%0], %1, 0x989680;\n\t" \
            "@P1 bra.uni WD_%=;\n\t" \
            "bra.uni WL_%=;\n\t" \
            "WD_%=:\n\t}" :: "r"(_m), "r"(_p) : "memory"); \
    } \
} while (0)
#define FENCE_PROXY_ASYNC() asm volatile("fence.proxy.async.shared::cta;" ::: "memory")
__device__ __forceinline__ void cp_bulk(uint32_t dst, const void* src, uint32_t bytes,
                                        uint32_t mbar) {
    asm volatile("cp.async.bulk.shared::cta.global.mbarrier::complete_tx::bytes "
                 "[%0], [%1], %2, [%3];"
                 :: "r"(dst), "l"(src), "r"(bytes), "r"(mbar) : "memory");
}
#define LDSM_X4(R, addr) \
    asm volatile("ldmatrix.sync.aligned.m8n8.x4.shared.b16 {%0,%1,%2,%3}, [%4];" \
        : "=r"((R)[0]), "=r"((R)[1]), "=r"((R)[2]), "=r"((R)[3]) : "r"(addr))
#define MMA16816(C, A, B0, B1) \
    asm volatile("mma.sync.aligned.m16n8k16.row.col.f32.bf16.bf16.f32 " \
        "{%0,%1,%2,%3},{%4,%5,%6,%7},{%8,%9},{%0,%1,%2,%3};" \
        : "+f"((C)[0]), "+f"((C)[1]), "+f"((C)[2]), "+f"((C)[3]) \
        : "r"((A)[0]), "r"((A)[1]), "r"((A)[2]), "r"((A)[3]), "r"(B0), "r"(B1))

// SW64 swizzle: 64B rows; 16B chunk c of row r -> c ^ ((r>>1)&3)
__device__ __forceinline__ uint32_t sw64_off(int row, int c) {
    return (uint32_t)(row * 64 + ((c ^ ((row >> 1) & 3)) << 4));
}

// MUFU-free tanh (FMA/ALU only), abs err ~2e-6
__device__ __forceinline__ float tanh_fma(float x) {
    float ax = fabsf(x);
    float y  = fminf(ax * 2.885390082f, 24.0f);
    float r  = y + 12582912.0f;
    int   ki = __float_as_int(r) - 0x4B400000;
    float f  = y - (r - 12582912.0f);
    float p  = 1.33218890e-3f;
    p = fmaf(p, f, 9.61812910e-3f);
    p = fmaf(p, f, 5.55041087e-2f);
    p = fmaf(p, f, 2.40226507e-1f);
    p = fmaf(p, f, 6.93147181e-1f);
    p = fmaf(p, f, 1.0f);
    float e   = __int_as_float(__float_as_int(p) + (ki << 23));
    float den = e + 1.0f;
    float z   = __int_as_float(0x7EF311C3 - __float_as_int(den));
    z = z * fmaf(-den, z, 2.0f);
    z = z * fmaf(-den, z, 2.0f);
    z = z * fmaf(-den, z, 2.0f);
    float t = fmaf(-2.0f, z, 1.0f);
    return copysignf(t, x);
}

__device__ __forceinline__ uint2 pack_hi_lo(float4 x, uint2* lo_out) {
    __nv_bfloat16 h0 = __float2bfloat16_rn(x.x), h1 = __float2bfloat16_rn(x.y);
    __nv_bfloat16 h2 = __float2bfloat16_rn(x.z), h3 = __float2bfloat16_rn(x.w);
    __nv_bfloat16 l0 = __float2bfloat16_rn(x.x - __bfloat162float(h0));
    __nv_bfloat16 l1 = __float2bfloat16_rn(x.y - __bfloat162float(h1));
    __nv_bfloat16 l2 = __float2bfloat16_rn(x.z - __bfloat162float(h2));
    __nv_bfloat16 l3 = __float2bfloat16_rn(x.w - __bfloat162float(h3));
    uint2 hi, lo;
    __nv_bfloat162 a(h0, h1), b(h2, h3), c(l0, l1), d(l2, l3);
    hi.x = *(uint32_t*)&a; hi.y = *(uint32_t*)&b;
    lo.x = *(uint32_t*)&c; lo.y = *(uint32_t*)&d;
    *lo_out = lo;
    return hi;
}

// ---------------------------------------------------------------------------
// split values -> tiled pre-swizzled hi/lo
// ---------------------------------------------------------------------------
__global__ void split_values_kernel(const float* __restrict__ v) {
    size_t i = ((size_t)blockIdx.x * 256 + threadIdx.x) * 4;
    float4 x = *(const float4*)(v + i);
    const int row = (int)(i >> 10), col = (int)(i & 1023);
    const int rb = row >> 7, r = row & 127;
    const int ch = col >> 5,  ci = col & 31;
    const int sw = (ci >> 3) ^ ((r >> 1) & 3);
    unsigned char* base = g_at + (((size_t)(rb * NCHUNK + ch)) << 14)
                               + r * 64 + sw * 16 + (ci & 7) * 2;
    uint2 lo;
    uint2 hi = pack_hi_lo(x, &lo);
    *(uint2*)base          = hi;
    *(uint2*)(base + 8192) = lo;
}

// ---------------------------------------------------------------------------
// W1 [k][u] -> tiled pre-swizzled transposed hi/lo
// ---------------------------------------------------------------------------
__global__ void split_w1t_kernel(const float* __restrict__ W1) {
    __shared__ float t[32][33];
    const int bx = blockIdx.x * 32, by = blockIdx.y * 32;  // bx: u, by: k
    const int tx = threadIdx.x, ty = threadIdx.y;
#pragma unroll
    for (int rr = 0; rr < 4; ++rr)
        t[ty + 8 * rr][tx] = W1[(size_t)(by + ty + 8 * rr) * UN + bx + tx];
    __syncthreads();
    // thread (tx, ty): u = bx+tx, k-group = by + ty*4 .. +3
    const int u = bx + tx, k0 = by + ty * 4;
    float4 x;
    x.x = t[ty * 4 + 0][tx]; x.y = t[ty * 4 + 1][tx];
    x.z = t[ty * 4 + 2][tx]; x.w = t[ty * 4 + 3][tx];
    const int ut = u >> 7, r = u & 127;
    const int ch = k0 >> 5, ci = k0 & 31;
    const int sw = (ci >> 3) ^ ((r >> 1) & 3);
    unsigned char* base = g_bt + (((size_t)(ut * NCHUNK + ch)) << 14)
                               + r * 64 + sw * 16 + (ci & 7) * 2;
    uint2 lo;
    uint2 hi = pack_hi_lo(x, &lo);
    *(uint2*)base          = hi;
    *(uint2*)(base + 8192) = lo;
}

// ---------------------------------------------------------------------------
__global__ void projq_kernel(const float* __restrict__ q,
                             const float* __restrict__ W2,
                             const float* __restrict__ b2) {
    const int u = blockIdx.x * 256 + threadIdx.x;
    const int b = blockIdx.y;
    const float* qb = q + b * DQ;
    float acc = b2[u];
#pragma unroll 8
    for (int d = 0; d < DQ; ++d)
        acc = fmaf(qb[d], W2[(size_t)d * UN + u], acc);
    g_projq[b * UN + u] = acc;
}

// ---------------------------------------------------------------------------
// score: bf16x3 HMMA, bulk-copy producer, mbarrier 3-stage pipeline.
// ---------------------------------------------------------------------------
__global__ __launch_bounds__(256, 2) void score_kernel(
    const float* __restrict__ b1g, const float* __restrict__ Vv) {

    extern __shared__ char smem[];
    const uint32_t sb    = smem_u32(smem);
    const uint32_t FULLB = sb;         // full[st] at sb + st*8
    const uint32_t EMPTB = sb + 24;    // empty[st] at sb + 24 + st*8
    const uint32_t SDATA = sb + 1024;

    const int tid = threadIdx.x, wid = tid >> 5, lane = tid & 31;
    const int u0   = blockIdx.x * BN;
    const int row0 = blockIdx.y * BM;
    const int b    = row0 >> 11;
    const int warp_m = wid & 1, warp_n = wid >> 1;

    const unsigned char* gA = g_at + (((size_t)blockIdx.y * NCHUNK) << 14);
    const unsigned char* gB = g_bt + (((size_t)blockIdx.x * NCHUNK) << 14);

    if (tid == 0) {
#pragma unroll
        for (int st = 0; st < NSTAGE; ++st) {
            MBARRIER_INIT(FULLB + st * 8, 1);
            MBARRIER_INIT(EMPTB + st * 8, 8);
        }
        FENCE_PROXY_ASYNC();
    }
    __syncthreads();

    // initial fills: chunks 0, 1
    if (tid == 0) {
#pragma unroll
        for (int t = 0; t < 2; ++t) {
            MBARRIER_EXPECT_TX(FULLB + t * 8, STAGE_BYTES);
            cp_bulk(SDATA + t * STAGE_BYTES,         gA + ((size_t)t << 14),
                    CHUNK_BYTES, FULLB + t * 8);
            cp_bulk(SDATA + t * STAGE_BYTES + 16384, gB + ((size_t)t << 14),
                    CHUNK_BYTES, FULLB + t * 8);
        }
    }

    // ldmatrix offsets
    const int lr = lane & 15, lh = lane >> 4;
    uint32_t aoff[4], boff[2];
#pragma unroll
    for (int mt = 0; mt < 4; ++mt)
        aoff[mt] = sw64_off(warp_m * 64 + mt * 16 + lr, lh);
#pragma unroll
    for (int bt = 0; bt < 2; ++bt)
        boff[bt] = sw64_off(warp_n * 32 + bt * 16 + lr, lh);

    float acc[4][4][4];
#pragma unroll
    for (int i = 0; i < 4; ++i)
#pragma unroll
        for (int j = 0; j < 4; ++j)
#pragma unroll
            for (int k = 0; k < 4; ++k) acc[i][j][k] = 0.0f;

    int st = 0, rnd = 0;       // consumer stage / round
    int st2 = 2, r2 = 0;       // producer prefetch stage / round (for chunk s+2)
    for (int s = 0; s < NCHUNK; ++s) {
        if (tid == 0 && s < NCHUNK - 2) {
            const int t = s + 2;
            if (r2 >= 1) MBARRIER_WAIT(EMPTB + st2 * 8, (r2 - 1) & 1);
            MBARRIER_EXPECT_TX(FULLB + st2 * 8, STAGE_BYTES);
            cp_bulk(SDATA + st2 * STAGE_BYTES,         gA + ((size_t)t << 14),
                    CHUNK_BYTES, FULLB + st2 * 8);
            cp_bulk(SDATA + st2 * STAGE_BYTES + 16384, gB + ((size_t)t << 14),
                    CHUNK_BYTES, FULLB + st2 * 8);
        }

        MBARRIER_WAIT(FULLB + st * 8, rnd & 1);
        const uint32_t sb_cp = SDATA + st * STAGE_BYTES;

#pragma unroll
        for (int ks = 0; ks < 2; ++ks) {
            const uint32_t kx = ks << 5;
            uint32_t a[4][4], bh[2][4], bl[2][4];
#pragma unroll
            for (int mt = 0; mt < 4; ++mt)
                LDSM_X4(a[mt], sb_cp + (aoff[mt] ^ kx));
#pragma unroll
            for (int bt = 0; bt < 2; ++bt) {
                LDSM_X4(bh[bt], sb_cp + 16384 + (boff[bt] ^ kx));
                LDSM_X4(bl[bt], sb_cp + 24576 + (boff[bt] ^ kx));
            }
#pragma unroll
            for (int mt = 0; mt < 4; ++mt)
#pragma unroll
                for (int nt = 0; nt < 4; ++nt) {
                    MMA16816(acc[mt][nt], a[mt],
                             bh[nt >> 1][nt & 1], bh[nt >> 1][(nt & 1) + 2]);
                    MMA16816(acc[mt][nt], a[mt],
                             bl[nt >> 1][nt & 1], bl[nt >> 1][(nt & 1) + 2]);
                }
#pragma unroll
            for (int mt = 0; mt < 4; ++mt)
                LDSM_X4(a[mt], sb_cp + 8192 + (aoff[mt] ^ kx));
#pragma unroll
            for (int mt = 0; mt < 4; ++mt)
#pragma unroll
                for (int nt = 0; nt < 4; ++nt)
                    MMA16816(acc[mt][nt], a[mt],
                             bh[nt >> 1][nt & 1], bh[nt >> 1][(nt & 1) + 2]);
        }

        if (lane == 0) MBARRIER_ARRIVE(EMPTB + st * 8);
        if (++st == NSTAGE) { st = 0; ++rnd; }
        if (tid == 0) { if (++st2 == NSTAGE) { st2 = 0; ++r2; } }
    }

    __syncthreads();   // all warps done with smem stages before reuse as `red`

    // ---------------- fused epilogue ----------------------------------------
    float tb[8], tv[8];
#pragma unroll
    for (int nt = 0; nt < 4; ++nt)
#pragma unroll
        for (int par = 0; par < 2; ++par) {
            const int u = u0 + warp_n * 32 + nt * 8 + (lane & 3) * 2 + par;
            tb[nt * 2 + par] = b1g[u] + g_projq[b * UN + u];
            tv[nt * 2 + par] = Vv[u];
        }

    float* red = (float*)(smem + 1024);
#pragma unroll
    for (int mt = 0; mt < 4; ++mt) {
        float s0 = 0.0f, s1 = 0.0f;
#pragma unroll
        for (int nt = 0; nt < 4; ++nt)
#pragma unroll
            for (int par = 0; par < 2; ++par) {
                const int j = nt * 2 + par;
                s0 = fmaf(tanh_fma(acc[mt][nt][par]     + tb[j]), tv[j], s0);
                s1 = fmaf(tanh_fma(acc[mt][nt][2 + par] + tb[j]), tv[j], s1);
            }
        s0 += __shfl_xor_sync(0xffffffff, s0, 1);
        s0 += __shfl_xor_sync(0xffffffff, s0, 2);
        s1 += __shfl_xor_sync(0xffffffff, s1, 1);
        s1 += __shfl_xor_sync(0xffffffff, s1, 2);
        if ((lane & 3) == 0) {
            const int r = warp_m * 64 + mt * 16 + (lane >> 2);
            red[r * 4 + warp_n]       = s0;
            red[(r + 8) * 4 + warp_n] = s1;
        }
    }
    __syncthreads();
    if (tid < 128) {
        const float s = (red[tid * 4 + 0] + red[tid * 4 + 1]) +
                        (red[tid * 4 + 2] + red[tid * 4 + 3]);
        g_spart[(size_t)(row0 + tid) * 8 + blockIdx.x] = s;
    }
}

// ---------------------------------------------------------------------------
__global__ void softmax_kernel(float* __restrict__ out_w) {
    const int b = blockIdx.x, tid = threadIdx.x;
    __shared__ float sm[256];
    float v[8];
    float lmax = -1e30f;
#pragma unroll
    for (int i = 0; i < 8; ++i) {
        const float* p = g_spart + (size_t)(b * SEQ + tid + i * 256) * 8;
        v[i] = ((p[0] + p[1]) + (p[2] + p[3])) + ((p[4] + p[5]) + (p[6] + p[7]));
        lmax = fmaxf(lmax, v[i]);
    }
    sm[tid] = lmax; __syncthreads();
    for (int s = 128; s > 0; s >>= 1) {
        if (tid < s) sm[tid] = fmaxf(sm[tid], sm[tid + s]);
        __syncthreads();
    }
    const float m = sm[0]; __syncthreads();
    float lsum = 0.0f;
#pragma unroll
    for (int i = 0; i < 8; ++i) { v[i] = __expf(v[i] - m); lsum += v[i]; }
    sm[tid] = lsum; __syncthreads();
    for (int s = 128; s > 0; s >>= 1) {
        if (tid < s) sm[tid] += sm[tid + s];
        __syncthreads();
    }
    const float inv = 1.0f / sm[0];
#pragma unroll
    for (int i = 0; i < 8; ++i)
        out_w[b * SEQ + tid + i * 256] = v[i] * inv;
}

// ---------------------------------------------------------------------------
__global__ void ctx_part_kernel(const float* __restrict__ values,
                                const float* __restrict__ w) {
    __shared__ float ws[32];
    const int sc = blockIdx.x, b = blockIdx.y, tid = threadIdx.x;
    if (tid < 32) ws[tid] = w[b * SEQ + sc * 32 + tid];
    __syncthreads();
    const int d0 = tid * 4;
    const float* base = values + (size_t)b * SEQ * DV + (size_t)sc * 32 * DV + d0;
    float4 acc = make_float4(0.f, 0.f, 0.f, 0.f);
#pragma unroll 8
    for (int s = 0; s < 32; ++s) {
        const float4 v = *(const float4*)(base + (size_t)s * DV);
        const float x = ws[s];
        acc.x = fmaf(x, v.x, acc.x); acc.y = fmaf(x, v.y, acc.y);
        acc.z = fmaf(x, v.z, acc.z); acc.w = fmaf(x, v.w, acc.w);
    }
    *(float4*)(g_cpart + (size_t)(sc * BATCH + b) * DV + d0) = acc;
}

__global__ void ctx_reduce_kernel(float* __restrict__ out_c) {
    const int idx = blockIdx.x * 256 + threadIdx.x;
    const int bb = idx >> 10, dd = idx & 1023;
    float s = 0.0f;
#pragma unroll 8
    for (int c = 0; c < NCTX; ++c)
        s += g_cpart[(size_t)(c * BATCH + bb) * DV + dd];
    out_c[idx] = s;
}

// ---------------------------------------------------------------------------
extern "C" void kernel_launch(void* const* d_in, const int* in_sizes, int n_in,
                              void* d_out, int out_size) {
    const float* query  = (const float*)d_in[0];
    const float* values = (const float*)d_in[1];
    const float* W1     = (const float*)d_in[2];
    const float* b1     = (const float*)d_in[3];
    const float* W2     = (const float*)d_in[4];
    const float* b2     = (const float*)d_in[5];
    const float* Vv     = (const float*)d_in[6];
    // d_in[7] = bV: cancels in softmax.

    float* out_c = (float*)d_out;
    float* out_w = out_c + BATCH * DV;

    static bool attr_set = false;
    if (!attr_set) {
        cudaFuncSetAttribute(score_kernel,
                             cudaFuncAttributeMaxDynamicSharedMemorySize, SMEM_BYTES);
        attr_set = true;
    }

    split_values_kernel<<<65536, 256>>>(values);
    split_w1t_kernel<<<dim3(32, 32), dim3(32, 8)>>>(W1);
    projq_kernel<<<dim3(4, BATCH), 256>>>(query, W2, b2);
    score_kernel<<<dim3(8, 512), 256, SMEM_BYTES>>>(b1, Vv);
    softmax_kernel<<<BATCH, 256>>>(out_w);
    ctx_part_kernel<<<dim3(NCTX, BATCH), 256>>>(values, out_w);
    ctx_reduce_kernel<<<128, 256>>>(out_c);
}

// round 6
// speedup vs baseline: 4.7125x; 1.2961x over previous
#include <cuda_runtime.h>
#include <cuda_fp16.h>
#include <math.h>
#include <stdint.h>

#define BATCH 32
#define SEQ   2048
#define DQ    1024
#define DV    1024
#define UN    1024
#define ROWS  (BATCH * SEQ)

#define BM 128
#define BN 128
#define BK 32
#define NCHUNK (DV / BK)              // 32
#define CHUNK_A 16384                 // Ah 8K | Al 8K
#define CHUNK_B 8192                  // Bh 8K
#define STAGE_BYTES (CHUNK_A + CHUNK_B)   // 24576
#define NSTAGE 4
#define SMEM_BYTES (1024 + NSTAGE * STAGE_BYTES)   // 99328
#define NCTX 64

// ---------------- device scratch ------------------------------------------
__device__ unsigned char g_at[(size_t)(ROWS / BM) * NCHUNK * CHUNK_A];  // 256MB
__device__ unsigned char g_bt[(size_t)(UN / BN) * NCHUNK * CHUNK_B];    // 2MB
__device__ float g_projq[BATCH * UN];
__device__ float g_spart[(size_t)ROWS * 8];
__device__ float g_cpart[(size_t)NCTX * BATCH * DV];

// ---------------- helpers ---------------------------------------------------
__device__ __forceinline__ uint32_t smem_u32(const void* p) {
    uint32_t a;
    asm("{ .reg .u64 t; cvta.to.shared.u64 t, %1; cvt.u32.u64 %0, t; }" : "=r"(a) : "l"(p));
    return a;
}
#define MBARRIER_INIT(addr, cnt) \
    asm volatile("mbarrier.init.shared.b64 [%0], %1;" :: "r"((uint32_t)(addr)), "r"((uint32_t)(cnt)) : "memory")
#define MBARRIER_ARRIVE(addr) \
    asm volatile("mbarrier.arrive.shared.b64 _, [%0];" :: "r"((uint32_t)(addr)) : "memory")
#define MBARRIER_EXPECT_TX(addr, tx) \
    asm volatile("mbarrier.arrive.expect_tx.shared.b64 _, [%0], %1;" :: "r"((uint32_t)(addr)), "r"((uint32_t)(tx)) : "memory")
#define MBARRIER_WAIT(addr, ph) do { \
    uint32_t _m = (uint32_t)(addr), _p = (uint32_t)(ph), _d; \
    asm volatile("{\n\t.reg .pred p;\n\t" \
        "mbarrier.try_wait.parity.acquire.cta.shared::cta.b64 p, [%1], %2;\n\t" \
        "selp.b32 %0, 1, 0, p;\n\t}" : "=r"(_d) : "r"(_m), "r"(_p) : "memory"); \
    if (!_d) { \
        asm volatile("{\n\t.reg .pred P1;\n\t" \
            "WL_%=:\n\t" \
            "mbarrier.try_wait.parity.acquire.cta.shared::cta.b64 P1, [%0], %1, 0x989680;\n\t" \
            "@P1 bra.uni WD_%=;\n\t" \
            "bra.uni WL_%=;\n\t" \
            "WD_%=:\n\t}" :: "r"(_m), "r"(_p) : "memory"); \
    } \
} while (0)
#define FENCE_PROXY_ASYNC() asm volatile("fence.proxy.async.shared::cta;" ::: "memory")
__device__ __forceinline__ void cp_bulk(uint32_t dst, const void* src, uint32_t bytes,
                                        uint32_t mbar) {
    asm volatile("cp.async.bulk.shared::cta.global.mbarrier::complete_tx::bytes "
                 "[%0], [%1], %2, [%3];"
                 :: "r"(dst), "l"(src), "r"(bytes), "r"(mbar) : "memory");
}
#define LDSM_X4(R, addr) \
    asm volatile("ldmatrix.sync.aligned.m8n8.x4.shared.b16 {%0,%1,%2,%3}, [%4];" \
        : "=r"((R)[0]), "=r"((R)[1]), "=r"((R)[2]), "=r"((R)[3]) : "r"(addr))
#define MMA16816(C, A, B0, B1) \
    asm volatile("mma.sync.aligned.m16n8k16.row.col.f32.f16.f16.f32 " \
        "{%0,%1,%2,%3},{%4,%5,%6,%7},{%8,%9},{%0,%1,%2,%3};" \
        : "+f"((C)[0]), "+f"((C)[1]), "+f"((C)[2]), "+f"((C)[3]) \
        : "r"((A)[0]), "r"((A)[1]), "r"((A)[2]), "r"((A)[3]), "r"(B0), "r"(B1))

// SW64 swizzle: 64B rows; 16B chunk c of row r -> c ^ ((r>>1)&3)
__device__ __forceinline__ uint32_t sw64_off(int row, int c) {
    return (uint32_t)(row * 64 + ((c ^ ((row >> 1) & 3)) << 4));
}

// MUFU-free tanh (FMA/ALU only), abs err ~2e-6
__device__ __forceinline__ float tanh_fma(float x) {
    float ax = fabsf(x);
    float y  = fminf(ax * 2.885390082f, 24.0f);
    float r  = y + 12582912.0f;
    int   ki = __float_as_int(r) - 0x4B400000;
    float f  = y - (r - 12582912.0f);
    float p  = 1.33218890e-3f;
    p = fmaf(p, f, 9.61812910e-3f);
    p = fmaf(p, f, 5.55041087e-2f);
    p = fmaf(p, f, 2.40226507e-1f);
    p = fmaf(p, f, 6.93147181e-1f);
    p = fmaf(p, f, 1.0f);
    float e   = __int_as_float(__float_as_int(p) + (ki << 23));
    float den = e + 1.0f;
    float z   = __int_as_float(0x7EF311C3 - __float_as_int(den));
    z = z * fmaf(-den, z, 2.0f);
    z = z * fmaf(-den, z, 2.0f);
    z = z * fmaf(-den, z, 2.0f);
    float t = fmaf(-2.0f, z, 1.0f);
    return copysignf(t, x);
}

// ---------------------------------------------------------------------------
// split values fp32 -> tiled pre-swizzled fp16 hi/lo
// ---------------------------------------------------------------------------
__global__ void split_values_kernel(const float* __restrict__ v) {
    size_t i = ((size_t)blockIdx.x * 256 + threadIdx.x) * 4;
    float4 x = *(const float4*)(v + i);
    const int row = (int)(i >> 10), col = (int)(i & 1023);
    const int rb = row >> 7, r = row & 127;
    const int ch = col >> 5,  ci = col & 31;
    const int sw = (ci >> 3) ^ ((r >> 1) & 3);
    unsigned char* base = g_at + ((size_t)(rb * NCHUNK + ch) * CHUNK_A)
                               + r * 64 + sw * 16 + (ci & 7) * 2;
    __half h0 = __float2half_rn(x.x), h1 = __float2half_rn(x.y);
    __half h2 = __float2half_rn(x.z), h3 = __float2half_rn(x.w);
    __half l0 = __float2half_rn(x.x - __half2float(h0));
    __half l1 = __float2half_rn(x.y - __half2float(h1));
    __half l2 = __float2half_rn(x.z - __half2float(h2));
    __half l3 = __float2half_rn(x.w - __half2float(h3));
    __half2 a = __halves2half2(h0, h1), bq = __halves2half2(h2, h3);
    __half2 c = __halves2half2(l0, l1), d  = __halves2half2(l2, l3);
    uint2 hi, lo;
    hi.x = *(uint32_t*)&a; hi.y = *(uint32_t*)&bq;
    lo.x = *(uint32_t*)&c; lo.y = *(uint32_t*)&d;
    *(uint2*)base          = hi;
    *(uint2*)(base + 8192) = lo;
}

// ---------------------------------------------------------------------------
// W1 [k][u] -> tiled pre-swizzled transposed fp16 (hi only)
// ---------------------------------------------------------------------------
__global__ void split_w1t_kernel(const float* __restrict__ W1) {
    __shared__ float t[32][33];
    const int bx = blockIdx.x * 32, by = blockIdx.y * 32;  // bx: u, by: k
    const int tx = threadIdx.x, ty = threadIdx.y;
#pragma unroll
    for (int rr = 0; rr < 4; ++rr)
        t[ty + 8 * rr][tx] = W1[(size_t)(by + ty + 8 * rr) * UN + bx + tx];
    __syncthreads();
    const int u = bx + tx, k0 = by + ty * 4;
    float4 x;
    x.x = t[ty * 4 + 0][tx]; x.y = t[ty * 4 + 1][tx];
    x.z = t[ty * 4 + 2][tx]; x.w = t[ty * 4 + 3][tx];
    const int ut = u >> 7, r = u & 127;
    const int ch = k0 >> 5, ci = k0 & 31;
    const int sw = (ci >> 3) ^ ((r >> 1) & 3);
    unsigned char* base = g_bt + ((size_t)(ut * NCHUNK + ch) * CHUNK_B)
                               + r * 64 + sw * 16 + (ci & 7) * 2;
    __half h0 = __float2half_rn(x.x), h1 = __float2half_rn(x.y);
    __half h2 = __float2half_rn(x.z), h3 = __float2half_rn(x.w);
    __half2 a = __halves2half2(h0, h1), bq = __halves2half2(h2, h3);
    uint2 hi;
    hi.x = *(uint32_t*)&a; hi.y = *(uint32_t*)&bq;
    *(uint2*)base = hi;
}

// ---------------------------------------------------------------------------
__global__ void projq_kernel(const float* __restrict__ q,
                             const float* __restrict__ W2,
                             const float* __restrict__ b2) {
    const int u = blockIdx.x * 256 + threadIdx.x;
    const int b = blockIdx.y;
    const float* qb = q + b * DQ;
    float acc = b2[u];
#pragma unroll 8
    for (int d = 0; d < DQ; ++d)
        acc = fmaf(qb[d], W2[(size_t)d * UN + u], acc);
    g_projq[b * UN + u] = acc;
}

// ---------------------------------------------------------------------------
// score: fp16 2-pass HMMA, dedicated producer warp, 4-stage mbarrier pipeline.
// 288 threads: warps 0-7 compute (64x32 warp tiles), warp 8 producer.
// ---------------------------------------------------------------------------
__global__ __launch_bounds__(288, 2) void score_kernel(
    const float* __restrict__ b1g, const float* __restrict__ Vv) {

    extern __shared__ char smem[];
    const uint32_t sb    = smem_u32(smem);
    const uint32_t FULLB = sb;          // full[st]  at sb + st*8
    const uint32_t EMPTB = sb + 32;     // empty[st] at sb + 32 + st*8
    const uint32_t SDATA = sb + 1024;

    const int tid = threadIdx.x, wid = tid >> 5, lane = tid & 31;
    const int u0   = blockIdx.x * BN;
    const int row0 = blockIdx.y * BM;
    const int b    = row0 >> 11;
    const int warp_m = wid & 1, warp_n = wid >> 1;   // valid for wid<8

    const unsigned char* gA = g_at + (size_t)blockIdx.y * NCHUNK * CHUNK_A;
    const unsigned char* gB = g_bt + (size_t)blockIdx.x * NCHUNK * CHUNK_B;

    if (tid == 0) {
#pragma unroll
        for (int st = 0; st < NSTAGE; ++st) {
            MBARRIER_INIT(FULLB + st * 8, 1);
            MBARRIER_INIT(EMPTB + st * 8, 8);
        }
        FENCE_PROXY_ASYNC();
    }
    __syncthreads();

    if (wid == 8) {
        // ---------------- producer warp -------------------------------------
        if (lane == 0) {
            for (int t = 0; t < NCHUNK; ++t) {
                const int st = t & 3, r = t >> 2;
                if (t >= NSTAGE) MBARRIER_WAIT(EMPTB + st * 8, (r - 1) & 1);
                const uint32_t dst = SDATA + st * STAGE_BYTES;
                MBARRIER_EXPECT_TX(FULLB + st * 8, STAGE_BYTES);
                cp_bulk(dst,           gA + (size_t)t * CHUNK_A, CHUNK_A,
                        FULLB + st * 8);
                cp_bulk(dst + CHUNK_A, gB + (size_t)t * CHUNK_B, CHUNK_B,
                        FULLB + st * 8);
            }
        }
    } else {
        // ---------------- compute warps -------------------------------------
        const int lr = lane & 15, lh = lane >> 4;
        uint32_t aoff[4], boff[2];
#pragma unroll
        for (int mt = 0; mt < 4; ++mt)
            aoff[mt] = sw64_off(warp_m * 64 + mt * 16 + lr, lh);
#pragma unroll
        for (int bt = 0; bt < 2; ++bt)
            boff[bt] = sw64_off(warp_n * 32 + bt * 16 + lr, lh);

        float acc[4][4][4];
#pragma unroll
        for (int i = 0; i < 4; ++i)
#pragma unroll
            for (int j = 0; j < 4; ++j)
#pragma unroll
                for (int k = 0; k < 4; ++k) acc[i][j][k] = 0.0f;

        for (int s = 0; s < NCHUNK; ++s) {
            const int st = s & 3;
            const uint32_t sb_cp = SDATA + st * STAGE_BYTES;
            MBARRIER_WAIT(FULLB + st * 8, (s >> 2) & 1);

#pragma unroll
            for (int ks = 0; ks < 2; ++ks) {
                const uint32_t kx = ks << 5;
                uint32_t a[4][4], bh[2][4];
#pragma unroll
                for (int mt = 0; mt < 4; ++mt)
                    LDSM_X4(a[mt], sb_cp + (aoff[mt] ^ kx));
#pragma unroll
                for (int bt = 0; bt < 2; ++bt)
                    LDSM_X4(bh[bt], sb_cp + CHUNK_A + (boff[bt] ^ kx));
                // pass 1: Ah * Bh
#pragma unroll
                for (int mt = 0; mt < 4; ++mt)
#pragma unroll
                    for (int nt = 0; nt < 4; ++nt)
                        MMA16816(acc[mt][nt], a[mt],
                                 bh[nt >> 1][nt & 1], bh[nt >> 1][(nt & 1) + 2]);
                // pass 2: Al * Bh (reuse a regs)
#pragma unroll
                for (int mt = 0; mt < 4; ++mt)
                    LDSM_X4(a[mt], sb_cp + 8192 + (aoff[mt] ^ kx));
#pragma unroll
                for (int mt = 0; mt < 4; ++mt)
#pragma unroll
                    for (int nt = 0; nt < 4; ++nt)
                        MMA16816(acc[mt][nt], a[mt],
                                 bh[nt >> 1][nt & 1], bh[nt >> 1][(nt & 1) + 2]);
            }
            if (lane == 0) MBARRIER_ARRIVE(EMPTB + st * 8);
        }

        // stash acc for epilogue below (fallthrough keeps regs live)
        __syncthreads();   // matches producer's sync below

        // ---------------- fused epilogue ------------------------------------
        float tb[8], tv[8];
#pragma unroll
        for (int nt = 0; nt < 4; ++nt)
#pragma unroll
            for (int par = 0; par < 2; ++par) {
                const int u = u0 + warp_n * 32 + nt * 8 + (lane & 3) * 2 + par;
                tb[nt * 2 + par] = b1g[u] + g_projq[b * UN + u];
                tv[nt * 2 + par] = Vv[u];
            }

        float* red = (float*)(smem + 1024);
#pragma unroll
        for (int mt = 0; mt < 4; ++mt) {
            float s0 = 0.0f, s1 = 0.0f;
#pragma unroll
            for (int nt = 0; nt < 4; ++nt)
#pragma unroll
                for (int par = 0; par < 2; ++par) {
                    const int j = nt * 2 + par;
                    s0 = fmaf(tanh_fma(acc[mt][nt][par]     + tb[j]), tv[j], s0);
                    s1 = fmaf(tanh_fma(acc[mt][nt][2 + par] + tb[j]), tv[j], s1);
                }
            s0 += __shfl_xor_sync(0xffffffff, s0, 1);
            s0 += __shfl_xor_sync(0xffffffff, s0, 2);
            s1 += __shfl_xor_sync(0xffffffff, s1, 1);
            s1 += __shfl_xor_sync(0xffffffff, s1, 2);
            if ((lane & 3) == 0) {
                const int r = warp_m * 64 + mt * 16 + (lane >> 2);
                red[r * 4 + warp_n]       = s0;
                red[(r + 8) * 4 + warp_n] = s1;
            }
        }
    }
    if (wid == 8) __syncthreads();   // producer joins first barrier
    __syncthreads();                  // red[] complete
    if (tid < 128) {
        float* red = (float*)(smem + 1024);
        const float s = (red[tid * 4 + 0] + red[tid * 4 + 1]) +
                        (red[tid * 4 + 2] + red[tid * 4 + 3]);
        g_spart[(size_t)(row0 + tid) * 8 + blockIdx.x] = s;
    }
}

// ---------------------------------------------------------------------------
__global__ void softmax_kernel(float* __restrict__ out_w) {
    const int b = blockIdx.x, tid = threadIdx.x;
    __shared__ float sm[256];
    float v[8];
    float lmax = -1e30f;
#pragma unroll
    for (int i = 0; i < 8; ++i) {
        const float* p = g_spart + (size_t)(b * SEQ + tid + i * 256) * 8;
        v[i] = ((p[0] + p[1]) + (p[2] + p[3])) + ((p[4] + p[5]) + (p[6] + p[7]));
        lmax = fmaxf(lmax, v[i]);
    }
    sm[tid] = lmax; __syncthreads();
    for (int s = 128; s > 0; s >>= 1) {
        if (tid < s) sm[tid] = fmaxf(sm[tid], sm[tid + s]);
        __syncthreads();
    }
    const float m = sm[0]; __syncthreads();
    float lsum = 0.0f;
#pragma unroll
    for (int i = 0; i < 8; ++i) { v[i] = __expf(v[i] - m); lsum += v[i]; }
    sm[tid] = lsum; __syncthreads();
    for (int s = 128; s > 0; s >>= 1) {
        if (tid < s) sm[tid] += sm[tid + s];
        __syncthreads();
    }
    const float inv = 1.0f / sm[0];
#pragma unroll
    for (int i = 0; i < 8; ++i)
        out_w[b * SEQ + tid + i * 256] = v[i] * inv;
}

// ---------------------------------------------------------------------------
__global__ void ctx_part_kernel(const float* __restrict__ values,
                                const float* __restrict__ w) {
    __shared__ float ws[32];
    const int sc = blockIdx.x, b = blockIdx.y, tid = threadIdx.x;
    if (tid < 32) ws[tid] = w[b * SEQ + sc * 32 + tid];
    __syncthreads();
    const int d0 = tid * 4;
    const float* base = values + (size_t)b * SEQ * DV + (size_t)sc * 32 * DV + d0;
    float4 acc = make_float4(0.f, 0.f, 0.f, 0.f);
#pragma unroll 8
    for (int s = 0; s < 32; ++s) {
        const float4 v = *(const float4*)(base + (size_t)s * DV);
        const float x = ws[s];
        acc.x = fmaf(x, v.x, acc.x); acc.y = fmaf(x, v.y, acc.y);
        acc.z = fmaf(x, v.z, acc.z); acc.w = fmaf(x, v.w, acc.w);
    }
    *(float4*)(g_cpart + (size_t)(sc * BATCH + b) * DV + d0) = acc;
}

__global__ void ctx_reduce_kernel(float* __restrict__ out_c) {
    const int idx = blockIdx.x * 256 + threadIdx.x;
    const int bb = idx >> 10, dd = idx & 1023;
    float s = 0.0f;
#pragma unroll 8
    for (int c = 0; c < NCTX; ++c)
        s += g_cpart[(size_t)(c * BATCH + bb) * DV + dd];
    out_c[idx] = s;
}

// ---------------------------------------------------------------------------
extern "C" void kernel_launch(void* const* d_in, const int* in_sizes, int n_in,
                              void* d_out, int out_size) {
    const float* query  = (const float*)d_in[0];
    const float* values = (const float*)d_in[1];
    const float* W1     = (const float*)d_in[2];
    const float* b1     = (const float*)d_in[3];
    const float* W2     = (const float*)d_in[4];
    const float* b2     = (const float*)d_in[5];
    const float* Vv     = (const float*)d_in[6];
    // d_in[7] = bV: cancels in softmax.

    float* out_c = (float*)d_out;
    float* out_w = out_c + BATCH * DV;

    static bool attr_set = false;
    if (!attr_set) {
        cudaFuncSetAttribute(score_kernel,
                             cudaFuncAttributeMaxDynamicSharedMemorySize, SMEM_BYTES);
        attr_set = true;
    }

    split_values_kernel<<<65536, 256>>>(values);
    split_w1t_kernel<<<dim3(32, 32), dim3(32, 8)>>>(W1);
    projq_kernel<<<dim3(4, BATCH), 256>>>(query, W2, b2);
    score_kernel<<<dim3(8, 512), 288, SMEM_BYTES>>>(b1, Vv);
    softmax_kernel<<<BATCH, 256>>>(out_w);
    ctx_part_kernel<<<dim3(NCTX, BATCH), 256>>>(values, out_w);
    ctx_reduce_kernel<<<128, 256>>>(out_c);
}

// round 7
// speedup vs baseline: 7.1048x; 1.5076x over previous
#include <cuda_runtime.h>
#include <cuda_fp16.h>
#include <math.h>
#include <stdint.h>

#define BATCH 32
#define SEQ   2048
#define DQ    1024
#define DV    1024
#define UN    1024
#define ROWS  (BATCH * SEQ)

#define BM 128
#define BN 128
#define BK 32
#define NCHUNK (DV / BK)              // 32
#define CHUNK_A 8192                  // A fp16 tile per chunk
#define CHUNK_B 8192                  // B fp16 tile per chunk
#define STAGE_BYTES (CHUNK_A + CHUNK_B)   // 16384
#define NSTAGE 6
#define SMEM_BYTES (1024 + NSTAGE * STAGE_BYTES)   // 99328
#define NCTX 64

// ---------------- device scratch ------------------------------------------
__device__ unsigned char g_at[(size_t)(ROWS / BM) * NCHUNK * CHUNK_A];  // 128MB
__device__ unsigned char g_bt[(size_t)(UN / BN) * NCHUNK * CHUNK_B];    // 2MB
__device__ float g_projq[BATCH * UN];
__device__ float g_spart[(size_t)ROWS * 8];
__device__ float g_cpart[(size_t)NCTX * BATCH * DV];

// ---------------- helpers ---------------------------------------------------
__device__ __forceinline__ uint32_t smem_u32(const void* p) {
    uint32_t a;
    asm("{ .reg .u64 t; cvta.to.shared.u64 t, %1; cvt.u32.u64 %0, t; }" : "=r"(a) : "l"(p));
    return a;
}
#define MBARRIER_INIT(addr, cnt) \
    asm volatile("mbarrier.init.shared.b64 [%0], %1;" :: "r"((uint32_t)(addr)), "r"((uint32_t)(cnt)) : "memory")
#define MBARRIER_ARRIVE(addr) \
    asm volatile("mbarrier.arrive.shared.b64 _, [%0];" :: "r"((uint32_t)(addr)) : "memory")
#define MBARRIER_EXPECT_TX(addr, tx) \
    asm volatile("mbarrier.arrive.expect_tx.shared.b64 _, [%0], %1;" :: "r"((uint32_t)(addr)), "r"((uint32_t)(tx)) : "memory")
#define MBARRIER_WAIT(addr, ph) do { \
    uint32_t _m = (uint32_t)(addr), _p = (uint32_t)(ph), _d; \
    asm volatile("{\n\t.reg .pred p;\n\t" \
        "mbarrier.try_wait.parity.acquire.cta.shared::cta.b64 p, [%1], %2;\n\t" \
        "selp.b32 %0, 1, 0, p;\n\t}" : "=r"(_d) : "r"(_m), "r"(_p) : "memory"); \
    if (!_d) { \
        asm volatile("{\n\t.reg .pred P1;\n\t" \
            "WL_%=:\n\t" \
            "mbarrier.try_wait.parity.acquire.cta.shared::cta.b64 P1, [%0], %1, 0x989680;\n\t" \
            "@P1 bra.uni WD_%=;\n\t" \
            "bra.uni WL_%=;\n\t" \
            "WD_%=:\n\t}" :: "r"(_m), "r"(_p) : "memory"); \
    } \
} while (0)
#define FENCE_PROXY_ASYNC() asm volatile("fence.proxy.async.shared::cta;" ::: "memory")
__device__ __forceinline__ void cp_bulk(uint32_t dst, const void* src, uint32_t bytes,
                                        uint32_t mbar) {
    asm volatile("cp.async.bulk.shared::cta.global.mbarrier::complete_tx::bytes "
                 "[%0], [%1], %2, [%3];"
                 :: "r"(dst), "l"(src), "r"(bytes), "r"(mbar) : "memory");
}
#define LDSM_X4(R, addr) \
    asm volatile("ldmatrix.sync.aligned.m8n8.x4.shared.b16 {%0,%1,%2,%3}, [%4];" \
        : "=r"((R)[0]), "=r"((R)[1]), "=r"((R)[2]), "=r"((R)[3]) : "r"(addr))
#define MMA16816(C, A, B0, B1) \
    asm volatile("mma.sync.aligned.m16n8k16.row.col.f32.f16.f16.f32 " \
        "{%0,%1,%2,%3},{%4,%5,%6,%7},{%8,%9},{%0,%1,%2,%3};" \
        : "+f"((C)[0]), "+f"((C)[1]), "+f"((C)[2]), "+f"((C)[3]) \
        : "r"((A)[0]), "r"((A)[1]), "r"((A)[2]), "r"((A)[3]), "r"(B0), "r"(B1))

// SW64 swizzle: 64B rows; 16B chunk c of row r -> c ^ ((r>>1)&3)
__device__ __forceinline__ uint32_t sw64_off(int row, int c) {
    return (uint32_t)(row * 64 + ((c ^ ((row >> 1) & 3)) << 4));
}

// MUFU-free tanh (FMA/ALU only), abs err ~2e-6
__device__ __forceinline__ float tanh_fma(float x) {
    float ax = fabsf(x);
    float y  = fminf(ax * 2.885390082f, 24.0f);
    float r  = y + 12582912.0f;
    int   ki = __float_as_int(r) - 0x4B400000;
    float f  = y - (r - 12582912.0f);
    float p  = 1.33218890e-3f;
    p = fmaf(p, f, 9.61812910e-3f);
    p = fmaf(p, f, 5.55041087e-2f);
    p = fmaf(p, f, 2.40226507e-1f);
    p = fmaf(p, f, 6.93147181e-1f);
    p = fmaf(p, f, 1.0f);
    float e   = __int_as_float(__float_as_int(p) + (ki << 23));
    float den = e + 1.0f;
    float z   = __int_as_float(0x7EF311C3 - __float_as_int(den));
    z = z * fmaf(-den, z, 2.0f);
    z = z * fmaf(-den, z, 2.0f);
    z = z * fmaf(-den, z, 2.0f);
    float t = fmaf(-2.0f, z, 1.0f);
    return copysignf(t, x);
}

// ---------------------------------------------------------------------------
// split values fp32 -> tiled pre-swizzled fp16
// ---------------------------------------------------------------------------
__global__ void split_values_kernel(const float* __restrict__ v) {
    size_t i = ((size_t)blockIdx.x * 256 + threadIdx.x) * 4;
    float4 x = *(const float4*)(v + i);
    const int row = (int)(i >> 10), col = (int)(i & 1023);
    const int rb = row >> 7, r = row & 127;
    const int ch = col >> 5,  ci = col & 31;
    const int sw = (ci >> 3) ^ ((r >> 1) & 3);
    unsigned char* base = g_at + ((size_t)(rb * NCHUNK + ch) * CHUNK_A)
                               + r * 64 + sw * 16 + (ci & 7) * 2;
    __half2 a = __halves2half2(__float2half_rn(x.x), __float2half_rn(x.y));
    __half2 b = __halves2half2(__float2half_rn(x.z), __float2half_rn(x.w));
    uint2 hi;
    hi.x = *(uint32_t*)&a; hi.y = *(uint32_t*)&b;
    *(uint2*)base = hi;
}

// ---------------------------------------------------------------------------
// W1 [k][u] -> tiled pre-swizzled transposed fp16
// ---------------------------------------------------------------------------
__global__ void split_w1t_kernel(const float* __restrict__ W1) {
    __shared__ float t[32][33];
    const int bx = blockIdx.x * 32, by = blockIdx.y * 32;  // bx: u, by: k
    const int tx = threadIdx.x, ty = threadIdx.y;
#pragma unroll
    for (int rr = 0; rr < 4; ++rr)
        t[ty + 8 * rr][tx] = W1[(size_t)(by + ty + 8 * rr) * UN + bx + tx];
    __syncthreads();
    const int u = bx + tx, k0 = by + ty * 4;
    float4 x;
    x.x = t[ty * 4 + 0][tx]; x.y = t[ty * 4 + 1][tx];
    x.z = t[ty * 4 + 2][tx]; x.w = t[ty * 4 + 3][tx];
    const int ut = u >> 7, r = u & 127;
    const int ch = k0 >> 5, ci = k0 & 31;
    const int sw = (ci >> 3) ^ ((r >> 1) & 3);
    unsigned char* base = g_bt + ((size_t)(ut * NCHUNK + ch) * CHUNK_B)
                               + r * 64 + sw * 16 + (ci & 7) * 2;
    __half2 a = __halves2half2(__float2half_rn(x.x), __float2half_rn(x.y));
    __half2 b = __halves2half2(__float2half_rn(x.z), __float2half_rn(x.w));
    uint2 hi;
    hi.x = *(uint32_t*)&a; hi.y = *(uint32_t*)&b;
    *(uint2*)base = hi;
}

// ---------------------------------------------------------------------------
__global__ void projq_kernel(const float* __restrict__ q,
                             const float* __restrict__ W2,
                             const float* __restrict__ b2) {
    const int u = blockIdx.x * 256 + threadIdx.x;
    const int b = blockIdx.y;
    const float* qb = q + b * DQ;
    float acc = b2[u];
#pragma unroll 8
    for (int d = 0; d < DQ; ++d)
        acc = fmaf(qb[d], W2[(size_t)d * UN + u], acc);
    g_projq[b * UN + u] = acc;
}

// ---------------------------------------------------------------------------
// score: fp16 single-pass HMMA, producer warp, 6-stage mbarrier pipeline.
// 288 threads: warps 0-7 compute (64x32 warp tiles), warp 8 producer.
// ---------------------------------------------------------------------------
__global__ __launch_bounds__(288, 2) void score_kernel(
    const float* __restrict__ b1g, const float* __restrict__ Vv) {

    extern __shared__ char smem[];
    const uint32_t sb    = smem_u32(smem);
    const uint32_t FULLB = sb;          // full[st]  at sb + st*8
    const uint32_t EMPTB = sb + 48;     // empty[st] at sb + 48 + st*8
    const uint32_t SDATA = sb + 1024;

    const int tid = threadIdx.x, wid = tid >> 5, lane = tid & 31;
    const int u0   = blockIdx.x * BN;
    const int row0 = blockIdx.y * BM;
    const int b    = row0 >> 11;
    const int warp_m = wid & 1, warp_n = wid >> 1;   // valid for wid<8

    const unsigned char* gA = g_at + (size_t)blockIdx.y * NCHUNK * CHUNK_A;
    const unsigned char* gB = g_bt + (size_t)blockIdx.x * NCHUNK * CHUNK_B;

    if (tid == 0) {
#pragma unroll
        for (int st = 0; st < NSTAGE; ++st) {
            MBARRIER_INIT(FULLB + st * 8, 1);
            MBARRIER_INIT(EMPTB + st * 8, 8);
        }
        FENCE_PROXY_ASYNC();
    }
    __syncthreads();

    if (wid == 8) {
        // ---------------- producer warp -------------------------------------
        if (lane == 0) {
            int st = 0, r = 0;
            for (int t = 0; t < NCHUNK; ++t) {
                if (t >= NSTAGE) MBARRIER_WAIT(EMPTB + st * 8, (r - 1) & 1);
                const uint32_t dst = SDATA + st * STAGE_BYTES;
                MBARRIER_EXPECT_TX(FULLB + st * 8, STAGE_BYTES);
                cp_bulk(dst,           gA + (size_t)t * CHUNK_A, CHUNK_A,
                        FULLB + st * 8);
                cp_bulk(dst + CHUNK_A, gB + (size_t)t * CHUNK_B, CHUNK_B,
                        FULLB + st * 8);
                if (++st == NSTAGE) { st = 0; ++r; }
            }
        }
    } else {
        // ---------------- compute warps -------------------------------------
        const int lr = lane & 15, lh = lane >> 4;
        uint32_t aoff[4], boff[2];
#pragma unroll
        for (int mt = 0; mt < 4; ++mt)
            aoff[mt] = sw64_off(warp_m * 64 + mt * 16 + lr, lh);
#pragma unroll
        for (int bt = 0; bt < 2; ++bt)
            boff[bt] = sw64_off(warp_n * 32 + bt * 16 + lr, lh);

        float acc[4][4][4];
#pragma unroll
        for (int i = 0; i < 4; ++i)
#pragma unroll
            for (int j = 0; j < 4; ++j)
#pragma unroll
                for (int k = 0; k < 4; ++k) acc[i][j][k] = 0.0f;

        int st = 0, rnd = 0;
        for (int s = 0; s < NCHUNK; ++s) {
            const uint32_t sb_cp = SDATA + st * STAGE_BYTES;
            MBARRIER_WAIT(FULLB + st * 8, rnd & 1);

#pragma unroll
            for (int ks = 0; ks < 2; ++ks) {
                const uint32_t kx = ks << 5;
                uint32_t a[4][4], bh[2][4];
#pragma unroll
                for (int mt = 0; mt < 4; ++mt)
                    LDSM_X4(a[mt], sb_cp + (aoff[mt] ^ kx));
#pragma unroll
                for (int bt = 0; bt < 2; ++bt)
                    LDSM_X4(bh[bt], sb_cp + CHUNK_A + (boff[bt] ^ kx));
#pragma unroll
                for (int mt = 0; mt < 4; ++mt)
#pragma unroll
                    for (int nt = 0; nt < 4; ++nt)
                        MMA16816(acc[mt][nt], a[mt],
                                 bh[nt >> 1][nt & 1], bh[nt >> 1][(nt & 1) + 2]);
            }
            if (lane == 0) MBARRIER_ARRIVE(EMPTB + st * 8);
            if (++st == NSTAGE) { st = 0; ++rnd; }
        }

        __syncthreads();   // joins producer sync below

        // ---------------- fused epilogue ------------------------------------
        float tb[8], tv[8];
#pragma unroll
        for (int nt = 0; nt < 4; ++nt)
#pragma unroll
            for (int par = 0; par < 2; ++par) {
                const int u = u0 + warp_n * 32 + nt * 8 + (lane & 3) * 2 + par;
                tb[nt * 2 + par] = b1g[u] + g_projq[b * UN + u];
                tv[nt * 2 + par] = Vv[u];
            }

        float* red = (float*)(smem + 1024);
#pragma unroll
        for (int mt = 0; mt < 4; ++mt) {
            float s0 = 0.0f, s1 = 0.0f;
#pragma unroll
            for (int nt = 0; nt < 4; ++nt)
#pragma unroll
                for (int par = 0; par < 2; ++par) {
                    const int j = nt * 2 + par;
                    s0 = fmaf(tanh_fma(acc[mt][nt][par]     + tb[j]), tv[j], s0);
                    s1 = fmaf(tanh_fma(acc[mt][nt][2 + par] + tb[j]), tv[j], s1);
                }
            s0 += __shfl_xor_sync(0xffffffff, s0, 1);
            s0 += __shfl_xor_sync(0xffffffff, s0, 2);
            s1 += __shfl_xor_sync(0xffffffff, s1, 1);
            s1 += __shfl_xor_sync(0xffffffff, s1, 2);
            if ((lane & 3) == 0) {
                const int r = warp_m * 64 + mt * 16 + (lane >> 2);
                red[r * 4 + warp_n]       = s0;
                red[(r + 8) * 4 + warp_n] = s1;
            }
        }
    }
    if (wid == 8) __syncthreads();   // producer joins first barrier
    __syncthreads();                  // red[] complete
    if (tid < 128) {
        float* red = (float*)(smem + 1024);
        const float s = (red[tid * 4 + 0] + red[tid * 4 + 1]) +
                        (red[tid * 4 + 2] + red[tid * 4 + 3]);
        g_spart[(size_t)(row0 + tid) * 8 + blockIdx.x] = s;
    }
}

// ---------------------------------------------------------------------------
__global__ void softmax_kernel(float* __restrict__ out_w) {
    const int b = blockIdx.x, tid = threadIdx.x;
    __shared__ float sm[256];
    float v[8];
    float lmax = -1e30f;
#pragma unroll
    for (int i = 0; i < 8; ++i) {
        const float* p = g_spart + (size_t)(b * SEQ + tid + i * 256) * 8;
        v[i] = ((p[0] + p[1]) + (p[2] + p[3])) + ((p[4] + p[5]) + (p[6] + p[7]));
        lmax = fmaxf(lmax, v[i]);
    }
    sm[tid] = lmax; __syncthreads();
    for (int s = 128; s > 0; s >>= 1) {
        if (tid < s) sm[tid] = fmaxf(sm[tid], sm[tid + s]);
        __syncthreads();
    }
    const float m = sm[0]; __syncthreads();
    float lsum = 0.0f;
#pragma unroll
    for (int i = 0; i < 8; ++i) { v[i] = __expf(v[i] - m); lsum += v[i]; }
    sm[tid] = lsum; __syncthreads();
    for (int s = 128; s > 0; s >>= 1) {
        if (tid < s) sm[tid] += sm[tid + s];
        __syncthreads();
    }
    const float inv = 1.0f / sm[0];
#pragma unroll
    for (int i = 0; i < 8; ++i)
        out_w[b * SEQ + tid + i * 256] = v[i] * inv;
}

// ---------------------------------------------------------------------------
__global__ void ctx_part_kernel(const float* __restrict__ values,
                                const float* __restrict__ w) {
    __shared__ float ws[32];
    const int sc = blockIdx.x, b = blockIdx.y, tid = threadIdx.x;
    if (tid < 32) ws[tid] = w[b * SEQ + sc * 32 + tid];
    __syncthreads();
    const int d0 = tid * 4;
    const float* base = values + (size_t)b * SEQ * DV + (size_t)sc * 32 * DV + d0;
    float4 acc = make_float4(0.f, 0.f, 0.f, 0.f);
#pragma unroll 8
    for (int s = 0; s < 32; ++s) {
        const float4 v = *(const float4*)(base + (size_t)s * DV);
        const float x = ws[s];
        acc.x = fmaf(x, v.x, acc.x); acc.y = fmaf(x, v.y, acc.y);
        acc.z = fmaf(x, v.z, acc.z); acc.w = fmaf(x, v.w, acc.w);
    }
    *(float4*)(g_cpart + (size_t)(sc * BATCH + b) * DV + d0) = acc;
}

__global__ void ctx_reduce_kernel(float* __restrict__ out_c) {
    const int idx = blockIdx.x * 256 + threadIdx.x;
    const int bb = idx >> 10, dd = idx & 1023;
    float s = 0.0f;
#pragma unroll 8
    for (int c = 0; c < NCTX; ++c)
        s += g_cpart[(size_t)(c * BATCH + bb) * DV + dd];
    out_c[idx] = s;
}

// ---------------------------------------------------------------------------
extern "C" void kernel_launch(void* const* d_in, const int* in_sizes, int n_in,
                              void* d_out, int out_size) {
    const float* query  = (const float*)d_in[0];
    const float* values = (const float*)d_in[1];
    const float* W1     = (const float*)d_in[2];
    const float* b1     = (const float*)d_in[3];
    const float* W2     = (const float*)d_in[4];
    const float* b2     = (const float*)d_in[5];
    const float* Vv     = (const float*)d_in[6];
    // d_in[7] = bV: cancels in softmax.

    float* out_c = (float*)d_out;
    float* out_w = out_c + BATCH * DV;

    static bool attr_set = false;
    if (!attr_set) {
        cudaFuncSetAttribute(score_kernel,
                             cudaFuncAttributeMaxDynamicSharedMemorySize, SMEM_BYTES);
        attr_set = true;
    }

    split_values_kernel<<<65536, 256>>>(values);
    split_w1t_kernel<<<dim3(32, 32), dim3(32, 8)>>>(W1);
    projq_kernel<<<dim3(4, BATCH), 256>>>(query, W2, b2);
    score_kernel<<<dim3(8, 512), 288, SMEM_BYTES>>>(b1, Vv);
    softmax_kernel<<<BATCH, 256>>>(out_w);
    ctx_part_kernel<<<dim3(NCTX, BATCH), 256>>>(values, out_w);
    ctx_reduce_kernel<<<128, 256>>>(out_c);
}

// round 8
// speedup vs baseline: 7.3836x; 1.0392x over previous
#include <cuda_runtime.h>
#include <cuda_fp16.h>
#include <math.h>
#include <stdint.h>

#define BATCH 32
#define SEQ   2048
#define DQ    1024
#define DV    1024
#define UN    1024
#define ROWS  (BATCH * SEQ)

#define BM 128
#define BN 128
#define CHUNK_A 8192                  // per 32-k sub-chunk
#define CHUNK_B 8192
#define NCHUNK (DV / 32)              // 32 sub-chunks
#define NSTEP  16                     // stages consumed (2 sub-chunks each)
#define STAGE_BYTES 32768             // A 16K | B 16K
#define NSTAGE 3
#define SMEM_BYTES (1024 + NSTAGE * STAGE_BYTES)   // 99328
#define NCTX 64

// ---------------- device scratch ------------------------------------------
__device__ unsigned char g_at[(size_t)(ROWS / BM) * NCHUNK * CHUNK_A];  // 128MB
__device__ unsigned char g_bt[(size_t)(UN / BN) * NCHUNK * CHUNK_B];    // 2MB
__device__ float g_projq[BATCH * UN];
__device__ float g_spart[(size_t)ROWS * 8];
__device__ float g_cpart[(size_t)NCTX * BATCH * DV];

// ---------------- helpers ---------------------------------------------------
__device__ __forceinline__ uint32_t smem_u32(const void* p) {
    uint32_t a;
    asm("{ .reg .u64 t; cvta.to.shared.u64 t, %1; cvt.u32.u64 %0, t; }" : "=r"(a) : "l"(p));
    return a;
}
#define MBARRIER_INIT(addr, cnt) \
    asm volatile("mbarrier.init.shared.b64 [%0], %1;" :: "r"((uint32_t)(addr)), "r"((uint32_t)(cnt)) : "memory")
#define MBARRIER_ARRIVE(addr) \
    asm volatile("mbarrier.arrive.shared.b64 _, [%0];" :: "r"((uint32_t)(addr)) : "memory")
#define MBARRIER_EXPECT_TX(addr, tx) \
    asm volatile("mbarrier.arrive.expect_tx.shared.b64 _, [%0], %1;" :: "r"((uint32_t)(addr)), "r"((uint32_t)(tx)) : "memory")
#define MBARRIER_WAIT(addr, ph) do { \
    uint32_t _m = (uint32_t)(addr), _p = (uint32_t)(ph), _d; \
    asm volatile("{\n\t.reg .pred p;\n\t" \
        "mbarrier.try_wait.parity.acquire.cta.shared::cta.b64 p, [%1], %2;\n\t" \
        "selp.b32 %0, 1, 0, p;\n\t}" : "=r"(_d) : "r"(_m), "r"(_p) : "memory"); \
    if (!_d) { \
        asm volatile("{\n\t.reg .pred P1;\n\t" \
            "WL_%=:\n\t" \
            "mbarrier.try_wait.parity.acquire.cta.shared::cta.b64 P1, [%0], %1, 0x989680;\n\t" \
            "@P1 bra.uni WD_%=;\n\t" \
            "bra.uni WL_%=;\n\t" \
            "WD_%=:\n\t}" :: "r"(_m), "r"(_p) : "memory"); \
    } \
} while (0)
#define FENCE_PROXY_ASYNC() asm volatile("fence.proxy.async.shared::cta;" ::: "memory")
__device__ __forceinline__ void cp_bulk(uint32_t dst, const void* src, uint32_t bytes,
                                        uint32_t mbar) {
    asm volatile("cp.async.bulk.shared::cta.global.mbarrier::complete_tx::bytes "
                 "[%0], [%1], %2, [%3];"
                 :: "r"(dst), "l"(src), "r"(bytes), "r"(mbar) : "memory");
}
#define LDSM_X4(R, addr) \
    asm volatile("ldmatrix.sync.aligned.m8n8.x4.shared.b16 {%0,%1,%2,%3}, [%4];" \
        : "=r"((R)[0]), "=r"((R)[1]), "=r"((R)[2]), "=r"((R)[3]) : "r"(addr))
#define MMA16816(C, A, B0, B1) \
    asm volatile("mma.sync.aligned.m16n8k16.row.col.f32.f16.f16.f32 " \
        "{%0,%1,%2,%3},{%4,%5,%6,%7},{%8,%9},{%0,%1,%2,%3};" \
        : "+f"((C)[0]), "+f"((C)[1]), "+f"((C)[2]), "+f"((C)[3]) \
        : "r"((A)[0]), "r"((A)[1]), "r"((A)[2]), "r"((A)[3]), "r"(B0), "r"(B1))

// SW64 swizzle: 64B rows; 16B chunk c of row r -> c ^ ((r>>1)&3)
__device__ __forceinline__ uint32_t sw64_off(int row, int c) {
    return (uint32_t)(row * 64 + ((c ^ ((row >> 1) & 3)) << 4));
}

// MUFU-free tanh (FMA/ALU only), abs err ~2e-6
__device__ __forceinline__ float tanh_fma(float x) {
    float ax = fabsf(x);
    float y  = fminf(ax * 2.885390082f, 24.0f);
    float r  = y + 12582912.0f;
    int   ki = __float_as_int(r) - 0x4B400000;
    float f  = y - (r - 12582912.0f);
    float p  = 1.33218890e-3f;
    p = fmaf(p, f, 9.61812910e-3f);
    p = fmaf(p, f, 5.55041087e-2f);
    p = fmaf(p, f, 2.40226507e-1f);
    p = fmaf(p, f, 6.93147181e-1f);
    p = fmaf(p, f, 1.0f);
    float e   = __int_as_float(__float_as_int(p) + (ki << 23));
    float den = e + 1.0f;
    float z   = __int_as_float(0x7EF311C3 - __float_as_int(den));
    z = z * fmaf(-den, z, 2.0f);
    z = z * fmaf(-den, z, 2.0f);
    z = z * fmaf(-den, z, 2.0f);
    float t = fmaf(-2.0f, z, 1.0f);
    return copysignf(t, x);
}

// ---------------------------------------------------------------------------
// split values fp32 -> tiled pre-swizzled fp16
// ---------------------------------------------------------------------------
__global__ void split_values_kernel(const float* __restrict__ v) {
    size_t i = ((size_t)blockIdx.x * 256 + threadIdx.x) * 4;
    float4 x = *(const float4*)(v + i);
    const int row = (int)(i >> 10), col = (int)(i & 1023);
    const int rb = row >> 7, r = row & 127;
    const int ch = col >> 5,  ci = col & 31;
    const int sw = (ci >> 3) ^ ((r >> 1) & 3);
    unsigned char* base = g_at + ((size_t)(rb * NCHUNK + ch) * CHUNK_A)
                               + r * 64 + sw * 16 + (ci & 7) * 2;
    __half2 a = __halves2half2(__float2half_rn(x.x), __float2half_rn(x.y));
    __half2 b = __halves2half2(__float2half_rn(x.z), __float2half_rn(x.w));
    uint2 hi;
    hi.x = *(uint32_t*)&a; hi.y = *(uint32_t*)&b;
    *(uint2*)base = hi;
}

// ---------------------------------------------------------------------------
// W1 [k][u] -> tiled pre-swizzled transposed fp16
// ---------------------------------------------------------------------------
__global__ void split_w1t_kernel(const float* __restrict__ W1) {
    __shared__ float t[32][33];
    const int bx = blockIdx.x * 32, by = blockIdx.y * 32;  // bx: u, by: k
    const int tx = threadIdx.x, ty = threadIdx.y;
#pragma unroll
    for (int rr = 0; rr < 4; ++rr)
        t[ty + 8 * rr][tx] = W1[(size_t)(by + ty + 8 * rr) * UN + bx + tx];
    __syncthreads();
    const int u = bx + tx, k0 = by + ty * 4;
    float4 x;
    x.x = t[ty * 4 + 0][tx]; x.y = t[ty * 4 + 1][tx];
    x.z = t[ty * 4 + 2][tx]; x.w = t[ty * 4 + 3][tx];
    const int ut = u >> 7, r = u & 127;
    const int ch = k0 >> 5, ci = k0 & 31;
    const int sw = (ci >> 3) ^ ((r >> 1) & 3);
    unsigned char* base = g_bt + ((size_t)(ut * NCHUNK + ch) * CHUNK_B)
                               + r * 64 + sw * 16 + (ci & 7) * 2;
    __half2 a = __halves2half2(__float2half_rn(x.x), __float2half_rn(x.y));
    __half2 b = __halves2half2(__float2half_rn(x.z), __float2half_rn(x.w));
    uint2 hi;
    hi.x = *(uint32_t*)&a; hi.y = *(uint32_t*)&b;
    *(uint2*)base = hi;
}

// ---------------------------------------------------------------------------
__global__ void projq_kernel(const float* __restrict__ q,
                             const float* __restrict__ W2,
                             const float* __restrict__ b2) {
    const int u = blockIdx.x * 256 + threadIdx.x;
    const int b = blockIdx.y;
    const float* qb = q + b * DQ;
    float acc = b2[u];
#pragma unroll 8
    for (int d = 0; d < DQ; ++d)
        acc = fmaf(qb[d], W2[(size_t)d * UN + u], acc);
    g_projq[b * UN + u] = acc;
}

// ---------------------------------------------------------------------------
// score: fp16 single-pass HMMA, producer warp, 3-stage x 64-k pipeline.
// 288 threads: warps 0-7 compute (64x32 warp tiles), warp 8 producer.
// ---------------------------------------------------------------------------
__global__ __launch_bounds__(288, 2) void score_kernel(
    const float* __restrict__ b1g, const float* __restrict__ Vv) {

    extern __shared__ char smem[];
    const uint32_t sb    = smem_u32(smem);
    const uint32_t FULLB = sb;          // full[st]  at sb + st*8
    const uint32_t EMPTB = sb + 24;     // empty[st] at sb + 24 + st*8
    const uint32_t SDATA = sb + 1024;

    const int tid = threadIdx.x, wid = tid >> 5, lane = tid & 31;
    const int u0   = blockIdx.x * BN;
    const int row0 = blockIdx.y * BM;
    const int b    = row0 >> 11;
    const int warp_m = wid & 1, warp_n = wid >> 1;   // valid for wid<8

    // stage covers 2 consecutive sub-chunks: contiguous 16KB in g_at/g_bt
    const unsigned char* gA = g_at + (size_t)blockIdx.y * NCHUNK * CHUNK_A;
    const unsigned char* gB = g_bt + (size_t)blockIdx.x * NCHUNK * CHUNK_B;

    if (tid == 0) {
#pragma unroll
        for (int st = 0; st < NSTAGE; ++st) {
            MBARRIER_INIT(FULLB + st * 8, 1);
            MBARRIER_INIT(EMPTB + st * 8, 8);
        }
        FENCE_PROXY_ASYNC();
    }
    __syncthreads();

    if (wid == 8) {
        // ---------------- producer warp -------------------------------------
        if (lane == 0) {
            int st = 0, r = 0;
            for (int t = 0; t < NSTEP; ++t) {
                if (t >= NSTAGE) MBARRIER_WAIT(EMPTB + st * 8, (r - 1) & 1);
                const uint32_t dst = SDATA + st * STAGE_BYTES;
                MBARRIER_EXPECT_TX(FULLB + st * 8, STAGE_BYTES);
                cp_bulk(dst,         gA + (size_t)t * 16384, 16384, FULLB + st * 8);
                cp_bulk(dst + 16384, gB + (size_t)t * 16384, 16384, FULLB + st * 8);
                if (++st == NSTAGE) { st = 0; ++r; }
            }
        }
    } else {
        // ---------------- compute warps -------------------------------------
        const int lr = lane & 15, lh = lane >> 4;
        uint32_t aoff[4], boff[2];
#pragma unroll
        for (int mt = 0; mt < 4; ++mt)
            aoff[mt] = sw64_off(warp_m * 64 + mt * 16 + lr, lh);
#pragma unroll
        for (int bt = 0; bt < 2; ++bt)
            boff[bt] = sw64_off(warp_n * 32 + bt * 16 + lr, lh);

        float acc[4][4][4];
#pragma unroll
        for (int i = 0; i < 4; ++i)
#pragma unroll
            for (int j = 0; j < 4; ++j)
#pragma unroll
                for (int k = 0; k < 4; ++k) acc[i][j][k] = 0.0f;

        int st = 0, rnd = 0;
        for (int s = 0; s < NSTEP; ++s) {
            const uint32_t sb_cp = SDATA + st * STAGE_BYTES;
            MBARRIER_WAIT(FULLB + st * 8, rnd & 1);

#pragma unroll
            for (int kslice = 0; kslice < 4; ++kslice) {
                const uint32_t sub = (kslice >> 1) * 8192;
                const uint32_t kx  = (kslice & 1) << 5;
                const uint32_t abase = sb_cp + sub;
                uint32_t a[4][4], bh[2][4];
#pragma unroll
                for (int mt = 0; mt < 4; ++mt)
                    LDSM_X4(a[mt], abase + (aoff[mt] ^ kx));
#pragma unroll
                for (int bt = 0; bt < 2; ++bt)
                    LDSM_X4(bh[bt], abase + 16384 + (boff[bt] ^ kx));
#pragma unroll
                for (int mt = 0; mt < 4; ++mt)
#pragma unroll
                    for (int nt = 0; nt < 4; ++nt)
                        MMA16816(acc[mt][nt], a[mt],
                                 bh[nt >> 1][nt & 1], bh[nt >> 1][(nt & 1) + 2]);
            }
            if (lane == 0) MBARRIER_ARRIVE(EMPTB + st * 8);
            if (++st == NSTAGE) { st = 0; ++rnd; }
        }

        __syncthreads();   // joins producer sync below

        // ---------------- fused epilogue ------------------------------------
        float tb[8], tv[8];
#pragma unroll
        for (int nt = 0; nt < 4; ++nt)
#pragma unroll
            for (int par = 0; par < 2; ++par) {
                const int u = u0 + warp_n * 32 + nt * 8 + (lane & 3) * 2 + par;
                tb[nt * 2 + par] = b1g[u] + g_projq[b * UN + u];
                tv[nt * 2 + par] = Vv[u];
            }

        float* red = (float*)(smem + 1024);
#pragma unroll
        for (int mt = 0; mt < 4; ++mt) {
            float s0 = 0.0f, s1 = 0.0f;
#pragma unroll
            for (int nt = 0; nt < 4; ++nt)
#pragma unroll
                for (int par = 0; par < 2; ++par) {
                    const int j = nt * 2 + par;
                    s0 = fmaf(tanh_fma(acc[mt][nt][par]     + tb[j]), tv[j], s0);
                    s1 = fmaf(tanh_fma(acc[mt][nt][2 + par] + tb[j]), tv[j], s1);
                }
            s0 += __shfl_xor_sync(0xffffffff, s0, 1);
            s0 += __shfl_xor_sync(0xffffffff, s0, 2);
            s1 += __shfl_xor_sync(0xffffffff, s1, 1);
            s1 += __shfl_xor_sync(0xffffffff, s1, 2);
            if ((lane & 3) == 0) {
                const int r = warp_m * 64 + mt * 16 + (lane >> 2);
                red[r * 4 + warp_n]       = s0;
                red[(r + 8) * 4 + warp_n] = s1;
            }
        }
    }
    if (wid == 8) __syncthreads();   // producer joins first barrier
    __syncthreads();                  // red[] complete
    if (tid < 128) {
        float* red = (float*)(smem + 1024);
        const float s = (red[tid * 4 + 0] + red[tid * 4 + 1]) +
                        (red[tid * 4 + 2] + red[tid * 4 + 3]);
        g_spart[(size_t)(row0 + tid) * 8 + blockIdx.x] = s;
    }
}

// ---------------------------------------------------------------------------
__global__ void softmax_kernel(float* __restrict__ out_w) {
    const int b = blockIdx.x, tid = threadIdx.x;
    __shared__ float sm[256];
    float v[8];
    float lmax = -1e30f;
#pragma unroll
    for (int i = 0; i < 8; ++i) {
        const float* p = g_spart + (size_t)(b * SEQ + tid + i * 256) * 8;
        v[i] = ((p[0] + p[1]) + (p[2] + p[3])) + ((p[4] + p[5]) + (p[6] + p[7]));
        lmax = fmaxf(lmax, v[i]);
    }
    sm[tid] = lmax; __syncthreads();
    for (int s = 128; s > 0; s >>= 1) {
        if (tid < s) sm[tid] = fmaxf(sm[tid], sm[tid + s]);
        __syncthreads();
    }
    const float m = sm[0]; __syncthreads();
    float lsum = 0.0f;
#pragma unroll
    for (int i = 0; i < 8; ++i) { v[i] = __expf(v[i] - m); lsum += v[i]; }
    sm[tid] = lsum; __syncthreads();
    for (int s = 128; s > 0; s >>= 1) {
        if (tid < s) sm[tid] += sm[tid + s];
        __syncthreads();
    }
    const float inv = 1.0f / sm[0];
#pragma unroll
    for (int i = 0; i < 8; ++i)
        out_w[b * SEQ + tid + i * 256] = v[i] * inv;
}

// ---------------------------------------------------------------------------
__global__ void ctx_part_kernel(const float* __restrict__ values,
                                const float* __restrict__ w) {
    __shared__ float ws[32];
    const int sc = blockIdx.x, b = blockIdx.y, tid = threadIdx.x;
    if (tid < 32) ws[tid] = w[b * SEQ + sc * 32 + tid];
    __syncthreads();
    const int d0 = tid * 4;
    const float* base = values + (size_t)b * SEQ * DV + (size_t)sc * 32 * DV + d0;
    float4 acc = make_float4(0.f, 0.f, 0.f, 0.f);
#pragma unroll 8
    for (int s = 0; s < 32; ++s) {
        const float4 v = *(const float4*)(base + (size_t)s * DV);
        const float x = ws[s];
        acc.x = fmaf(x, v.x, acc.x); acc.y = fmaf(x, v.y, acc.y);
        acc.z = fmaf(x, v.z, acc.z); acc.w = fmaf(x, v.w, acc.w);
    }
    *(float4*)(g_cpart + (size_t)(sc * BATCH + b) * DV + d0) = acc;
}

__global__ void ctx_reduce_kernel(float* __restrict__ out_c) {
    const int idx = blockIdx.x * 256 + threadIdx.x;
    const int bb = idx >> 10, dd = idx & 1023;
    float s = 0.0f;
#pragma unroll 8
    for (int c = 0; c < NCTX; ++c)
        s += g_cpart[(size_t)(c * BATCH + bb) * DV + dd];
    out_c[idx] = s;
}

// ---------------------------------------------------------------------------
extern "C" void kernel_launch(void* const* d_in, const int* in_sizes, int n_in,
                              void* d_out, int out_size) {
    const float* query  = (const float*)d_in[0];
    const float* values = (const float*)d_in[1];
    const float* W1     = (const float*)d_in[2];
    const float* b1     = (const float*)d_in[3];
    const float* W2     = (const float*)d_in[4];
    const float* b2     = (const float*)d_in[5];
    const float* Vv     = (const float*)d_in[6];
    // d_in[7] = bV: cancels in softmax.

    float* out_c = (float*)d_out;
    float* out_w = out_c + BATCH * DV;

    static bool attr_set = false;
    if (!attr_set) {
        cudaFuncSetAttribute(score_kernel,
                             cudaFuncAttributeMaxDynamicSharedMemorySize, SMEM_BYTES);
        attr_set = true;
    }

    split_values_kernel<<<65536, 256>>>(values);
    split_w1t_kernel<<<dim3(32, 32), dim3(32, 8)>>>(W1);
    projq_kernel<<<dim3(4, BATCH), 256>>>(query, W2, b2);
    score_kernel<<<dim3(8, 512), 288, SMEM_BYTES>>>(b1, Vv);
    softmax_kernel<<<BATCH, 256>>>(out_w);
    ctx_part_kernel<<<dim3(NCTX, BATCH), 256>>>(values, out_w);
    ctx_reduce_kernel<<<128, 256>>>(out_c);
}